// round 3
// baseline (speedup 1.0000x reference)
#include <cuda_runtime.h>
#include <cstdint>

#define N_NODES 50000
#define N_EDGES 800000
#define E_TOT   (N_EDGES + N_NODES)   // self loops appended
#define HID     96
#define NEG_SLOPE 0.2f

// ---------------- scratch (allocation-free: device globals) ----------------
__device__ float    g_x[N_NODES * HID];   // current layer input features
__device__ float    g_h[N_NODES * HID];   // h = x @ W (reused as [N] for final layer)
__device__ float    g_out[N_NODES * HID]; // aggregation accumulator
__device__ float    g_es[N_NODES];
__device__ float    g_ed[N_NODES];
__device__ unsigned g_m[N_NODES];         // order-encoded segment max
__device__ float    g_s[N_NODES];         // segment sum of exp
__device__ float    g_e[E_TOT];           // per-edge logit, then exp value

// order-preserving float <-> uint encoding for atomicMax on floats
__device__ __forceinline__ unsigned f2o(float f) {
    unsigned u = __float_as_uint(f);
    return (u & 0x80000000u) ? ~u : (u | 0x80000000u);
}
__device__ __forceinline__ float o2f(unsigned u) {
    return __uint_as_float((u & 0x80000000u) ? (u & 0x7fffffffu) : ~u);
}

// ---------------- K1: h = x@W, logits es/ed, init m/s/out ----------------
template<int IN, bool FROM_GX>
__global__ void gemm_logits(const float* __restrict__ xin,
                            const float* __restrict__ W,
                            const float* __restrict__ as_,
                            const float* __restrict__ ad_,
                            const float* __restrict__ b) {
    __shared__ float xs[IN];
    __shared__ float red_s[3], red_d[3];
    int n = blockIdx.x;
    int j = threadIdx.x;                       // 0..95
    const float* xrow = FROM_GX ? (g_x + (size_t)n * IN) : (xin + (size_t)n * IN);
    if (j < IN) xs[j] = xrow[j];
    __syncthreads();
    float acc = 0.f;
#pragma unroll
    for (int k = 0; k < IN; k++) acc += xs[k] * W[k * HID + j];
    g_h[(size_t)n * HID + j] = acc;
    g_out[(size_t)n * HID + j] = b[j];

    float ps = acc * as_[j];
    float pd = acc * ad_[j];
#pragma unroll
    for (int o = 16; o; o >>= 1) {
        ps += __shfl_down_sync(0xffffffffu, ps, o);
        pd += __shfl_down_sync(0xffffffffu, pd, o);
    }
    int w = j >> 5;
    if ((j & 31) == 0) { red_s[w] = ps; red_d[w] = pd; }
    __syncthreads();
    if (j == 0) {
        g_es[n] = red_s[0] + red_s[1] + red_s[2];
        g_ed[n] = red_d[0] + red_d[1] + red_d[2];
        g_s[n] = 0.f;
        g_m[n] = 0u;   // encoded: below every real float
    }
}

// final layer: out_dim = 1, warp per node
__global__ void gemm_logits_f(const float* __restrict__ W,
                              const float* __restrict__ as_,
                              const float* __restrict__ ad_,
                              const float* __restrict__ b,
                              float* __restrict__ dout) {
    int n = blockIdx.x * (blockDim.x >> 5) + (threadIdx.x >> 5);
    if (n >= N_NODES) return;
    int lane = threadIdx.x & 31;
    float acc = 0.f;
#pragma unroll
    for (int k = lane; k < HID; k += 32) acc += g_x[(size_t)n * HID + k] * W[k];
#pragma unroll
    for (int o = 16; o; o >>= 1) acc += __shfl_down_sync(0xffffffffu, acc, o);
    if (lane == 0) {
        g_h[n]  = acc;
        g_es[n] = acc * as_[0];
        g_ed[n] = acc * ad_[0];
        g_s[n]  = 0.f;
        g_m[n]  = 0u;
        dout[n] = b[0];
    }
}

// edge_index is int32 (JAX x64 disabled: jnp.int64 lowers to int32), shape [2, E]
__device__ __forceinline__ void edge_sd(const int* __restrict__ ei, int i,
                                        int& s, int& d) {
    if (i < N_EDGES) { s = __ldg(ei + i); d = __ldg(ei + N_EDGES + i); }
    else             { s = d = i - N_EDGES; }
}

// ---------------- K2: per-edge leaky-relu logit + segment max ----------------
__global__ void edge_max(const int* __restrict__ ei) {
    int i = blockIdx.x * blockDim.x + threadIdx.x;
    if (i >= E_TOT) return;
    int s, d; edge_sd(ei, i, s, d);
    float e = g_es[s] + g_ed[d];
    e = (e > 0.f) ? e : NEG_SLOPE * e;
    g_e[i] = e;
    atomicMax(&g_m[d], f2o(e));
}

// ---------------- K3: exp + segment sum ----------------
__global__ void edge_expsum(const int* __restrict__ ei) {
    int i = blockIdx.x * blockDim.x + threadIdx.x;
    if (i >= E_TOT) return;
    int d;
    if (i < N_EDGES) d = __ldg(ei + N_EDGES + i); else d = i - N_EDGES;
    float ex = __expf(g_e[i] - o2f(g_m[d]));
    g_e[i] = ex;
    atomicAdd(&g_s[d], ex);
}

// ---------------- K4: out[dst] += alpha * h[src]  (warp per edge, 96 feats) --
__global__ void aggregate96(const int* __restrict__ ei) {
    int i = blockIdx.x * (blockDim.x >> 5) + (threadIdx.x >> 5);
    if (i >= E_TOT) return;
    int lane = threadIdx.x & 31;
    int s, d; edge_sd(ei, i, s, d);
    float alpha = g_e[i] / g_s[d];
    const float* hs = g_h + (size_t)s * HID;
    float* od = g_out + (size_t)d * HID;
    atomicAdd(od + lane,      alpha * hs[lane]);
    atomicAdd(od + lane + 32, alpha * hs[lane + 32]);
    atomicAdd(od + lane + 64, alpha * hs[lane + 64]);
}

// final layer aggregation: 1 feature, thread per edge, accumulate into d_out
__global__ void aggregate1(const int* __restrict__ ei, float* __restrict__ dout) {
    int i = blockIdx.x * blockDim.x + threadIdx.x;
    if (i >= E_TOT) return;
    int s, d; edge_sd(ei, i, s, d);
    float alpha = g_e[i] / g_s[d];
    atomicAdd(&dout[d], alpha * g_h[s]);
}

// ---------------- K5: epilogue: residual + relu, write next-layer input ------
__global__ void epilogue(int residual) {
    int idx = blockIdx.x * blockDim.x + threadIdx.x;
    if (idx >= N_NODES * HID) return;
    float v = g_out[idx];
    if (residual) v += g_x[idx];
    g_x[idx] = fmaxf(v, 0.f);
}

// ---------------- launch ----------------
extern "C" void kernel_launch(void* const* d_in, const int* in_sizes, int n_in,
                              void* d_out, int out_size) {
    const float* x  = (const float*)d_in[0];
    const int*   ei = (const int*)d_in[1];   // int32 [2, E]
    // d_in[2] = edge_weight (ignored, matches reference)
    const float* W0 = (const float*)d_in[3];
    const float* as0 = (const float*)d_in[4];
    const float* ad0 = (const float*)d_in[5];
    const float* b0 = (const float*)d_in[6];
    const float* W1 = (const float*)d_in[7];
    const float* as1 = (const float*)d_in[8];
    const float* ad1 = (const float*)d_in[9];
    const float* b1 = (const float*)d_in[10];
    const float* W2 = (const float*)d_in[11];
    const float* as2 = (const float*)d_in[12];
    const float* ad2 = (const float*)d_in[13];
    const float* b2 = (const float*)d_in[14];
    const float* Wf = (const float*)d_in[15];
    const float* asf = (const float*)d_in[16];
    const float* adf = (const float*)d_in[17];
    const float* bf = (const float*)d_in[18];
    float* dout = (float*)d_out;

    const int EB = 256;
    const int EGRID  = (E_TOT + EB - 1) / EB;               // thread-per-edge
    const int WGRID  = (E_TOT + (EB / 32) - 1) / (EB / 32); // warp-per-edge
    const int NWARP  = (N_NODES + (EB / 32) - 1) / (EB / 32);
    const int FGRID  = (N_NODES * HID + EB - 1) / EB;

    // ---- layer 0 (in=32, no residual) ----
    gemm_logits<32, false><<<N_NODES, HID>>>(x, W0, as0, ad0, b0);
    edge_max<<<EGRID, EB>>>(ei);
    edge_expsum<<<EGRID, EB>>>(ei);
    aggregate96<<<WGRID, EB>>>(ei);
    epilogue<<<FGRID, EB>>>(0);

    // ---- layer 1 (in=96, residual) ----
    gemm_logits<96, true><<<N_NODES, HID>>>(nullptr, W1, as1, ad1, b1);
    edge_max<<<EGRID, EB>>>(ei);
    edge_expsum<<<EGRID, EB>>>(ei);
    aggregate96<<<WGRID, EB>>>(ei);
    epilogue<<<FGRID, EB>>>(1);

    // ---- layer 2 (in=96, residual) ----
    gemm_logits<96, true><<<N_NODES, HID>>>(nullptr, W2, as2, ad2, b2);
    edge_max<<<EGRID, EB>>>(ei);
    edge_expsum<<<EGRID, EB>>>(ei);
    aggregate96<<<WGRID, EB>>>(ei);
    epilogue<<<FGRID, EB>>>(1);

    // ---- final layer (out=1) ----
    gemm_logits_f<<<NWARP, EB>>>(Wf, asf, adf, bf, dout);
    edge_max<<<EGRID, EB>>>(ei);
    edge_expsum<<<EGRID, EB>>>(ei);
    aggregate1<<<EGRID, EB>>>(ei, dout);
}

// round 5
// speedup vs baseline: 1.6175x; 1.6175x over previous
#include <cuda_runtime.h>
#include <cstdint>

#define N_NODES 50000
#define N_EDGES 800000
#define E_TOT   (N_EDGES + N_NODES)   // self loops appended
#define HID     96
#define NEG_SLOPE 0.2f

// ---------------- scratch (allocation-free: device globals) ----------------
__device__ float g_x[N_NODES * HID];   // current layer input features
__device__ float g_h[N_NODES * HID];   // h = x @ W ([N] for final layer)
__device__ float g_es[N_NODES];
__device__ float g_ed[N_NODES];
// CSR (built once per launch; edges are launch-invariant)
__device__ int g_cnt[N_NODES];
__device__ int g_rp [N_NODES + 1];
__device__ int g_cur[N_NODES];
__device__ int g_csrc[E_TOT];

__device__ __forceinline__ float lrelu(float e) {
    return (e > 0.f) ? e : NEG_SLOPE * e;
}

// ---------------- CSR build ----------------
__global__ void csr_zero() {
    int i = blockIdx.x * blockDim.x + threadIdx.x;
    if (i < N_NODES) g_cnt[i] = 0;
}

__global__ void csr_hist(const int* __restrict__ ei) {
    int i = blockIdx.x * blockDim.x + threadIdx.x;
    if (i >= E_TOT) return;
    int d = (i < N_EDGES) ? __ldg(ei + N_EDGES + i) : (i - N_EDGES);
    atomicAdd(&g_cnt[d], 1);
}

// single-block exclusive scan of g_cnt -> g_rp, g_cur
__global__ void csr_scan() {
    __shared__ int part[1024];
    const int CH = (N_NODES + 1023) / 1024;   // 49
    int t = threadIdx.x;
    int base = t * CH;
    int sum = 0;
    for (int c = 0; c < CH; c++) {
        int idx = base + c;
        if (idx < N_NODES) sum += g_cnt[idx];
    }
    part[t] = sum;
    __syncthreads();
    for (int off = 1; off < 1024; off <<= 1) {
        int v = (t >= off) ? part[t - off] : 0;
        __syncthreads();
        if (t >= off) part[t] += v;
        __syncthreads();
    }
    int run = (t > 0) ? part[t - 1] : 0;
    for (int c = 0; c < CH; c++) {
        int idx = base + c;
        if (idx < N_NODES) {
            g_rp[idx]  = run;
            g_cur[idx] = run;
            run += g_cnt[idx];
        }
    }
    if (t == 1023) g_rp[N_NODES] = E_TOT;
}

__global__ void csr_scatter(const int* __restrict__ ei) {
    int i = blockIdx.x * blockDim.x + threadIdx.x;
    if (i >= E_TOT) return;
    int s, d;
    if (i < N_EDGES) { s = __ldg(ei + i); d = __ldg(ei + N_EDGES + i); }
    else             { s = d = i - N_EDGES; }
    int pos = atomicAdd(&g_cur[d], 1);
    g_csrc[pos] = s;
}

// ---------------- K1: h = x@W, logits es/ed ----------------
template<int IN, bool FROM_GX>
__global__ void gemm_logits(const float* __restrict__ xin,
                            const float* __restrict__ W,
                            const float* __restrict__ as_,
                            const float* __restrict__ ad_) {
    __shared__ float xs[IN];
    __shared__ float red_s[3], red_d[3];
    int n = blockIdx.x;
    int j = threadIdx.x;                       // 0..95
    const float* xrow = FROM_GX ? (g_x + (size_t)n * IN) : (xin + (size_t)n * IN);
    if (j < IN) xs[j] = xrow[j];
    __syncthreads();
    float acc = 0.f;
#pragma unroll
    for (int k = 0; k < IN; k++) acc += xs[k] * W[k * HID + j];
    g_h[(size_t)n * HID + j] = acc;

    float ps = acc * as_[j];
    float pd = acc * ad_[j];
#pragma unroll
    for (int o = 16; o; o >>= 1) {
        ps += __shfl_down_sync(0xffffffffu, ps, o);
        pd += __shfl_down_sync(0xffffffffu, pd, o);
    }
    int w = j >> 5;
    if ((j & 31) == 0) { red_s[w] = ps; red_d[w] = pd; }
    __syncthreads();
    if (j == 0) {
        g_es[n] = red_s[0] + red_s[1] + red_s[2];
        g_ed[n] = red_d[0] + red_d[1] + red_d[2];
    }
}

// final layer gemm: out_dim = 1, warp per node
__global__ void gemm_logits_f(const float* __restrict__ W,
                              const float* __restrict__ as_,
                              const float* __restrict__ ad_) {
    int n = blockIdx.x * (blockDim.x >> 5) + (threadIdx.x >> 5);
    if (n >= N_NODES) return;
    int lane = threadIdx.x & 31;
    float acc = 0.f;
#pragma unroll
    for (int k = lane; k < HID; k += 32) acc += g_x[(size_t)n * HID + k] * W[k];
#pragma unroll
    for (int o = 16; o; o >>= 1) acc += __shfl_down_sync(0xffffffffu, acc, o);
    if (lane == 0) {
        g_h[n]  = acc;
        g_es[n] = acc * as_[0];
        g_ed[n] = acc * ad_[0];
    }
}

// ---------------- fused attention + aggregation (wide layers) ----------------
// warp per dst node: segment-softmax + weighted gather, no atomics.
template<bool RESIDUAL>
__global__ void gat_fused96(const float* __restrict__ b) {
    int n = blockIdx.x * (blockDim.x >> 5) + (threadIdx.x >> 5);
    if (n >= N_NODES) return;
    int lane = threadIdx.x & 31;
    int beg = g_rp[n], end = g_rp[n + 1];
    float edv = g_ed[n];

    // pass A: segment max
    float m = -1e30f;
    for (int i = beg + lane; i < end; i += 32)
        m = fmaxf(m, lrelu(g_es[g_csrc[i]] + edv));
#pragma unroll
    for (int o = 16; o; o >>= 1)
        m = fmaxf(m, __shfl_xor_sync(0xffffffffu, m, o));

    // pass B: s = sum(exp), num[j] = sum(exp * h[src][j])
    float s = 0.f, a0 = 0.f, a1 = 0.f, a2 = 0.f;
    for (int i = beg; i < end; i++) {
        int src = g_csrc[i];                       // broadcast load
        float ex = __expf(lrelu(g_es[src] + edv) - m);
        s += ex;
        const float* h = g_h + (size_t)src * HID;
        a0 = fmaf(ex, h[lane],      a0);
        a1 = fmaf(ex, h[lane + 32], a1);
        a2 = fmaf(ex, h[lane + 64], a2);
    }
    float inv = 1.f / s;
    float* xr = g_x + (size_t)n * HID;
    float v0 = a0 * inv + b[lane];
    float v1 = a1 * inv + b[lane + 32];
    float v2 = a2 * inv + b[lane + 64];
    if (RESIDUAL) { v0 += xr[lane]; v1 += xr[lane + 32]; v2 += xr[lane + 64]; }
    xr[lane]      = fmaxf(v0, 0.f);
    xr[lane + 32] = fmaxf(v1, 0.f);
    xr[lane + 64] = fmaxf(v2, 0.f);
}

// final layer: out_dim = 1, lanes parallel over edges
__global__ void gat_fused1(const float* __restrict__ b, float* __restrict__ dout) {
    int n = blockIdx.x * (blockDim.x >> 5) + (threadIdx.x >> 5);
    if (n >= N_NODES) return;
    int lane = threadIdx.x & 31;
    int beg = g_rp[n], end = g_rp[n + 1];
    float edv = g_ed[n];

    float m = -1e30f;
    for (int i = beg + lane; i < end; i += 32)
        m = fmaxf(m, lrelu(g_es[g_csrc[i]] + edv));
#pragma unroll
    for (int o = 16; o; o >>= 1)
        m = fmaxf(m, __shfl_xor_sync(0xffffffffu, m, o));

    float s = 0.f, num = 0.f;
    for (int i = beg + lane; i < end; i += 32) {
        int src = g_csrc[i];
        float ex = __expf(lrelu(g_es[src] + edv) - m);
        s += ex;
        num = fmaf(ex, g_h[src], num);
    }
#pragma unroll
    for (int o = 16; o; o >>= 1) {
        s   += __shfl_xor_sync(0xffffffffu, s, o);
        num += __shfl_xor_sync(0xffffffffu, num, o);
    }
    if (lane == 0) dout[n] = num / s + b[0];
}

// ---------------- launch ----------------
extern "C" void kernel_launch(void* const* d_in, const int* in_sizes, int n_in,
                              void* d_out, int out_size) {
    const float* x  = (const float*)d_in[0];
    const int*   ei = (const int*)d_in[1];   // int32 [2, E]
    // d_in[2] = edge_weight (ignored, matches reference)
    const float* W0 = (const float*)d_in[3];
    const float* as0 = (const float*)d_in[4];
    const float* ad0 = (const float*)d_in[5];
    const float* b0 = (const float*)d_in[6];
    const float* W1 = (const float*)d_in[7];
    const float* as1 = (const float*)d_in[8];
    const float* ad1 = (const float*)d_in[9];
    const float* b1 = (const float*)d_in[10];
    const float* W2 = (const float*)d_in[11];
    const float* as2 = (const float*)d_in[12];
    const float* ad2 = (const float*)d_in[13];
    const float* b2 = (const float*)d_in[14];
    const float* Wf = (const float*)d_in[15];
    const float* asf = (const float*)d_in[16];
    const float* adf = (const float*)d_in[17];
    const float* bf = (const float*)d_in[18];
    float* dout = (float*)d_out;

    const int EB = 256;
    const int EGRID = (E_TOT + EB - 1) / EB;               // thread-per-edge
    const int WGRID = (N_NODES + (EB / 32) - 1) / (EB / 32); // warp-per-node
    const int ZGRID = (N_NODES + EB - 1) / EB;

    // ---- CSR build (once; edges identical for all layers) ----
    csr_zero<<<ZGRID, EB>>>();
    csr_hist<<<EGRID, EB>>>(ei);
    csr_scan<<<1, 1024>>>();
    csr_scatter<<<EGRID, EB>>>(ei);

    // ---- layer 0 (in=32, no residual) ----
    gemm_logits<32, false><<<N_NODES, HID>>>(x, W0, as0, ad0);
    gat_fused96<false><<<WGRID, EB>>>(b0);

    // ---- layer 1 (in=96, residual) ----
    gemm_logits<96, true><<<N_NODES, HID>>>(nullptr, W1, as1, ad1);
    gat_fused96<true><<<WGRID, EB>>>(b1);

    // ---- layer 2 (in=96, residual) ----
    gemm_logits<96, true><<<N_NODES, HID>>>(nullptr, W2, as2, ad2);
    gat_fused96<true><<<WGRID, EB>>>(b2);

    // ---- final layer (out=1) ----
    gemm_logits_f<<<WGRID, EB>>>(Wf, asf, adf);
    gat_fused1<<<WGRID, EB>>>(bf, dout);
}

// round 6
// speedup vs baseline: 1.8982x; 1.1735x over previous
#include <cuda_runtime.h>
#include <cstdint>

#define N_NODES 50000
#define N_EDGES 800000
#define E_TOT   (N_EDGES + N_NODES)   // self loops appended
#define HID     96
#define NEG_SLOPE 0.2f

// ---------------- scratch (allocation-free: device globals) ----------------
__device__ float g_x[N_NODES * HID];   // current layer input features
__device__ float g_h[N_NODES * HID];   // h = x @ W ([N] for final layer)
__device__ float g_es[N_NODES];
__device__ float g_ed[N_NODES];
// CSR (built once per launch; edges are launch-invariant)
__device__ int g_cnt[N_NODES];
__device__ int g_rp [N_NODES + 1];
__device__ int g_cur[N_NODES];
__device__ int g_csrc[E_TOT];

__device__ __forceinline__ float lrelu(float e) {
    return (e > 0.f) ? e : NEG_SLOPE * e;
}

// ---------------- CSR build ----------------
__global__ void csr_zero() {
    int i = blockIdx.x * blockDim.x + threadIdx.x;
    if (i < N_NODES) g_cnt[i] = 0;
}

__global__ void csr_hist(const int* __restrict__ ei) {
    int i = blockIdx.x * blockDim.x + threadIdx.x;
    if (i >= E_TOT) return;
    int d = (i < N_EDGES) ? __ldg(ei + N_EDGES + i) : (i - N_EDGES);
    atomicAdd(&g_cnt[d], 1);
}

// single-block exclusive scan of g_cnt -> g_rp, g_cur
__global__ void csr_scan() {
    __shared__ int part[1024];
    const int CH = (N_NODES + 1023) / 1024;   // 49
    int t = threadIdx.x;
    int base = t * CH;
    int sum = 0;
    for (int c = 0; c < CH; c++) {
        int idx = base + c;
        if (idx < N_NODES) sum += g_cnt[idx];
    }
    part[t] = sum;
    __syncthreads();
    for (int off = 1; off < 1024; off <<= 1) {
        int v = (t >= off) ? part[t - off] : 0;
        __syncthreads();
        if (t >= off) part[t] += v;
        __syncthreads();
    }
    int run = (t > 0) ? part[t - 1] : 0;
    for (int c = 0; c < CH; c++) {
        int idx = base + c;
        if (idx < N_NODES) {
            g_rp[idx]  = run;
            g_cur[idx] = run;
            run += g_cnt[idx];
        }
    }
    if (t == 1023) g_rp[N_NODES] = E_TOT;
}

__global__ void csr_scatter(const int* __restrict__ ei) {
    int i = blockIdx.x * blockDim.x + threadIdx.x;
    if (i >= E_TOT) return;
    int s, d;
    if (i < N_EDGES) { s = __ldg(ei + i); d = __ldg(ei + N_EDGES + i); }
    else             { s = d = i - N_EDGES; }
    int pos = atomicAdd(&g_cur[d], 1);
    g_csrc[pos] = s;
}

// ---------------- register-blocked GEMM: h = x @ W  ----------------
// 256 threads, 64 nodes/block, thread computes 4 nodes x 6 cols.
// x tile staged in shared (padded stride 97); W read via L1 (36KB resident).
template<int K, bool FROM_GX>
__global__ __launch_bounds__(256) void gemm_tiled(const float* __restrict__ xin,
                                                  const float* __restrict__ W) {
    __shared__ float xs[64][K + 1];
    int t  = threadIdx.x;
    int nb = blockIdx.x * 64;

    const float* xsrc = FROM_GX ? g_x : xin;
    for (int idx = t; idx < 64 * K; idx += 256) {
        int n = idx / K, k = idx % K;
        int gn = nb + n;
        xs[n][k] = (gn < N_NODES) ? xsrc[(size_t)gn * K + k] : 0.f;
    }
    __syncthreads();

    int c = t & 15;     // col group: cols c + 16u, u=0..5
    int r = t >> 4;     // node group: nodes r*4+v, v=0..3

    float acc[4][6];
#pragma unroll
    for (int v = 0; v < 4; v++)
#pragma unroll
        for (int u = 0; u < 6; u++) acc[v][u] = 0.f;

#pragma unroll 4
    for (int k = 0; k < K; k++) {
        float xv[4], wv[6];
#pragma unroll
        for (int v = 0; v < 4; v++) xv[v] = xs[r * 4 + v][k];
#pragma unroll
        for (int u = 0; u < 6; u++) wv[u] = __ldg(&W[k * HID + c + 16 * u]);
#pragma unroll
        for (int v = 0; v < 4; v++)
#pragma unroll
            for (int u = 0; u < 6; u++)
                acc[v][u] = fmaf(xv[v], wv[u], acc[v][u]);
    }

#pragma unroll
    for (int v = 0; v < 4; v++) {
        int n = nb + r * 4 + v;
        if (n < N_NODES) {
#pragma unroll
            for (int u = 0; u < 6; u++)
                g_h[(size_t)n * HID + c + 16 * u] = acc[v][u];
        }
    }
}

// ---------------- logits: es = h.as, ed = h.ad (warp per node) ----------------
__global__ void logits_kernel(const float* __restrict__ as_,
                              const float* __restrict__ ad_) {
    int n = blockIdx.x * (blockDim.x >> 5) + (threadIdx.x >> 5);
    if (n >= N_NODES) return;
    int lane = threadIdx.x & 31;
    const float* h = g_h + (size_t)n * HID;
    float h0 = h[lane], h1 = h[lane + 32], h2 = h[lane + 64];
    float ps = h0 * __ldg(as_ + lane) + h1 * __ldg(as_ + lane + 32) + h2 * __ldg(as_ + lane + 64);
    float pd = h0 * __ldg(ad_ + lane) + h1 * __ldg(ad_ + lane + 32) + h2 * __ldg(ad_ + lane + 64);
#pragma unroll
    for (int o = 16; o; o >>= 1) {
        ps += __shfl_xor_sync(0xffffffffu, ps, o);
        pd += __shfl_xor_sync(0xffffffffu, pd, o);
    }
    if (lane == 0) { g_es[n] = ps; g_ed[n] = pd; }
}

// final layer gemm: out_dim = 1, warp per node
__global__ void gemm_logits_f(const float* __restrict__ W,
                              const float* __restrict__ as_,
                              const float* __restrict__ ad_) {
    int n = blockIdx.x * (blockDim.x >> 5) + (threadIdx.x >> 5);
    if (n >= N_NODES) return;
    int lane = threadIdx.x & 31;
    float acc = 0.f;
#pragma unroll
    for (int k = lane; k < HID; k += 32) acc += g_x[(size_t)n * HID + k] * __ldg(W + k);
#pragma unroll
    for (int o = 16; o; o >>= 1) acc += __shfl_down_sync(0xffffffffu, acc, o);
    if (lane == 0) {
        g_h[n]  = acc;
        g_es[n] = acc * __ldg(as_);
        g_ed[n] = acc * __ldg(ad_);
    }
}

// ---------------- fused attention + aggregation (wide layers) ----------------
// warp per dst node: segment-softmax + weighted gather, no atomics.
template<bool RESIDUAL>
__global__ void gat_fused96(const float* __restrict__ b) {
    int n = blockIdx.x * (blockDim.x >> 5) + (threadIdx.x >> 5);
    if (n >= N_NODES) return;
    int lane = threadIdx.x & 31;
    int beg = g_rp[n], end = g_rp[n + 1];
    float edv = g_ed[n];

    // pass A: segment max (lanes parallel over edges)
    float m = -1e30f;
    for (int i = beg + lane; i < end; i += 32)
        m = fmaxf(m, lrelu(g_es[g_csrc[i]] + edv));
#pragma unroll
    for (int o = 16; o; o >>= 1)
        m = fmaxf(m, __shfl_xor_sync(0xffffffffu, m, o));

    // pass B: s = sum(exp), num[j] = sum(exp * h[src][j]); unrolled x2 for MLP
    float s = 0.f, a0 = 0.f, a1 = 0.f, a2 = 0.f;
    int i = beg;
    for (; i + 2 <= end; i += 2) {
        int s0 = g_csrc[i];
        int s1 = g_csrc[i + 1];
        float e0 = __expf(lrelu(g_es[s0] + edv) - m);
        float e1 = __expf(lrelu(g_es[s1] + edv) - m);
        const float* h0 = g_h + (size_t)s0 * HID;
        const float* h1 = g_h + (size_t)s1 * HID;
        float x00 = h0[lane], x01 = h0[lane + 32], x02 = h0[lane + 64];
        float x10 = h1[lane], x11 = h1[lane + 32], x12 = h1[lane + 64];
        s += e0 + e1;
        a0 = fmaf(e0, x00, a0); a1 = fmaf(e0, x01, a1); a2 = fmaf(e0, x02, a2);
        a0 = fmaf(e1, x10, a0); a1 = fmaf(e1, x11, a1); a2 = fmaf(e1, x12, a2);
    }
    if (i < end) {
        int s0 = g_csrc[i];
        float e0 = __expf(lrelu(g_es[s0] + edv) - m);
        const float* h0 = g_h + (size_t)s0 * HID;
        s += e0;
        a0 = fmaf(e0, h0[lane], a0);
        a1 = fmaf(e0, h0[lane + 32], a1);
        a2 = fmaf(e0, h0[lane + 64], a2);
    }
    float inv = 1.f / s;
    float* xr = g_x + (size_t)n * HID;
    float v0 = a0 * inv + __ldg(b + lane);
    float v1 = a1 * inv + __ldg(b + lane + 32);
    float v2 = a2 * inv + __ldg(b + lane + 64);
    if (RESIDUAL) { v0 += xr[lane]; v1 += xr[lane + 32]; v2 += xr[lane + 64]; }
    xr[lane]      = fmaxf(v0, 0.f);
    xr[lane + 32] = fmaxf(v1, 0.f);
    xr[lane + 64] = fmaxf(v2, 0.f);
}

// final layer: out_dim = 1, lanes parallel over edges
__global__ void gat_fused1(const float* __restrict__ b, float* __restrict__ dout) {
    int n = blockIdx.x * (blockDim.x >> 5) + (threadIdx.x >> 5);
    if (n >= N_NODES) return;
    int lane = threadIdx.x & 31;
    int beg = g_rp[n], end = g_rp[n + 1];
    float edv = g_ed[n];

    float m = -1e30f;
    for (int i = beg + lane; i < end; i += 32)
        m = fmaxf(m, lrelu(g_es[g_csrc[i]] + edv));
#pragma unroll
    for (int o = 16; o; o >>= 1)
        m = fmaxf(m, __shfl_xor_sync(0xffffffffu, m, o));

    float s = 0.f, num = 0.f;
    for (int i = beg + lane; i < end; i += 32) {
        int src = g_csrc[i];
        float ex = __expf(lrelu(g_es[src] + edv) - m);
        s += ex;
        num = fmaf(ex, g_h[src], num);
    }
#pragma unroll
    for (int o = 16; o; o >>= 1) {
        s   += __shfl_xor_sync(0xffffffffu, s, o);
        num += __shfl_xor_sync(0xffffffffu, num, o);
    }
    if (lane == 0) dout[n] = num / s + __ldg(b);
}

// ---------------- launch ----------------
extern "C" void kernel_launch(void* const* d_in, const int* in_sizes, int n_in,
                              void* d_out, int out_size) {
    const float* x  = (const float*)d_in[0];
    const int*   ei = (const int*)d_in[1];   // int32 [2, E]
    // d_in[2] = edge_weight (ignored, matches reference)
    const float* W0 = (const float*)d_in[3];
    const float* as0 = (const float*)d_in[4];
    const float* ad0 = (const float*)d_in[5];
    const float* b0 = (const float*)d_in[6];
    const float* W1 = (const float*)d_in[7];
    const float* as1 = (const float*)d_in[8];
    const float* ad1 = (const float*)d_in[9];
    const float* b1 = (const float*)d_in[10];
    const float* W2 = (const float*)d_in[11];
    const float* as2 = (const float*)d_in[12];
    const float* ad2 = (const float*)d_in[13];
    const float* b2 = (const float*)d_in[14];
    const float* Wf = (const float*)d_in[15];
    const float* asf = (const float*)d_in[16];
    const float* adf = (const float*)d_in[17];
    const float* bf = (const float*)d_in[18];
    float* dout = (float*)d_out;

    const int EB = 256;
    const int EGRID = (E_TOT + EB - 1) / EB;                 // thread-per-edge
    const int WGRID = (N_NODES + (EB / 32) - 1) / (EB / 32); // warp-per-node
    const int ZGRID = (N_NODES + EB - 1) / EB;
    const int GGRID = (N_NODES + 63) / 64;                   // 64 nodes per gemm block

    // ---- CSR build (once; edges identical for all layers) ----
    csr_zero<<<ZGRID, EB>>>();
    csr_hist<<<EGRID, EB>>>(ei);
    csr_scan<<<1, 1024>>>();
    csr_scatter<<<EGRID, EB>>>(ei);

    // ---- layer 0 (in=32, no residual) ----
    gemm_tiled<32, false><<<GGRID, 256>>>(x, W0);
    logits_kernel<<<WGRID, EB>>>(as0, ad0);
    gat_fused96<false><<<WGRID, EB>>>(b0);

    // ---- layer 1 (in=96, residual) ----
    gemm_tiled<96, true><<<GGRID, 256>>>(nullptr, W1);
    logits_kernel<<<WGRID, EB>>>(as1, ad1);
    gat_fused96<true><<<WGRID, EB>>>(b1);

    // ---- layer 2 (in=96, residual) ----
    gemm_tiled<96, true><<<GGRID, 256>>>(nullptr, W2);
    logits_kernel<<<WGRID, EB>>>(as2, ad2);
    gat_fused96<true><<<WGRID, EB>>>(b2);

    // ---- final layer (out=1) ----
    gemm_logits_f<<<WGRID, EB>>>(Wf, asf, adf);
    gat_fused1<<<WGRID, EB>>>(bf, dout);
}

// round 7
// speedup vs baseline: 2.2119x; 1.1653x over previous
#include <cuda_runtime.h>
#include <cstdint>

#define N_NODES 50000
#define N_EDGES 800000
#define E_TOT   (N_EDGES + N_NODES)   // self loops appended
#define HID     96
#define NEG_SLOPE 0.2f

// ---------------- scratch (allocation-free: device globals) ----------------
__device__ float g_x[N_NODES * HID];   // current layer input features
__device__ float g_h[N_NODES * HID];   // h = x @ W ([N] for final layer)
__device__ float g_es[N_NODES];
__device__ float g_ed[N_NODES];
// CSR (rebuilt every launch; edges are launch-invariant inputs)
__device__ int g_cnt[N_NODES];
__device__ int g_rp [N_NODES + 1];
__device__ int g_cur[N_NODES];
__device__ int g_csrc[E_TOT];

__device__ __forceinline__ float lrelu(float e) {
    return (e > 0.f) ? e : NEG_SLOPE * e;
}

// packed f32x2 helpers (FFMA2 is PTX-only on sm_103a)
__device__ __forceinline__ unsigned long long pack2(float lo, float hi) {
    unsigned long long r;
    asm("mov.b64 %0, {%1, %2};" : "=l"(r) : "f"(lo), "f"(hi));
    return r;
}
__device__ __forceinline__ void unpack2(unsigned long long v, float& lo, float& hi) {
    asm("mov.b64 {%0, %1}, %2;" : "=f"(lo), "=f"(hi) : "l"(v));
}
__device__ __forceinline__ unsigned long long fma2(unsigned long long a,
                                                   unsigned long long b,
                                                   unsigned long long c) {
    unsigned long long d;
    asm("fma.rn.f32x2 %0, %1, %2, %3;" : "=l"(d) : "l"(a), "l"(b), "l"(c));
    return d;
}

// ---------------- CSR build ----------------
__global__ void csr_zero() {
    int i = blockIdx.x * blockDim.x + threadIdx.x;
    if (i < N_NODES) g_cnt[i] = 0;
}

__global__ void csr_hist(const int* __restrict__ ei) {
    int i = blockIdx.x * blockDim.x + threadIdx.x;
    if (i >= E_TOT) return;
    int d = (i < N_EDGES) ? __ldg(ei + N_EDGES + i) : (i - N_EDGES);
    atomicAdd(&g_cnt[d], 1);
}

// single-block exclusive scan of g_cnt -> g_rp, g_cur
__global__ void csr_scan() {
    __shared__ int part[1024];
    const int CH = (N_NODES + 1023) / 1024;   // 49
    int t = threadIdx.x;
    int base = t * CH;
    int sum = 0;
    for (int c = 0; c < CH; c++) {
        int idx = base + c;
        if (idx < N_NODES) sum += g_cnt[idx];
    }
    part[t] = sum;
    __syncthreads();
    for (int off = 1; off < 1024; off <<= 1) {
        int v = (t >= off) ? part[t - off] : 0;
        __syncthreads();
        if (t >= off) part[t] += v;
        __syncthreads();
    }
    int run = (t > 0) ? part[t - 1] : 0;
    for (int c = 0; c < CH; c++) {
        int idx = base + c;
        if (idx < N_NODES) {
            g_rp[idx]  = run;
            g_cur[idx] = run;
            run += g_cnt[idx];
        }
    }
    if (t == 1023) g_rp[N_NODES] = E_TOT;
}

__global__ void csr_scatter(const int* __restrict__ ei) {
    int i = blockIdx.x * blockDim.x + threadIdx.x;
    if (i >= E_TOT) return;
    int s, d;
    if (i < N_EDGES) { s = __ldg(ei + i); d = __ldg(ei + N_EDGES + i); }
    else             { s = d = i - N_EDGES; }
    int pos = atomicAdd(&g_cur[d], 1);
    g_csrc[pos] = s;
}

// ---------------- GEMM + fused logits: h = x@W, es = h.as, ed = h.ad --------
// 256 threads, 64 nodes/block. Thread t: c = t&15 -> col pairs {2c,2c+1}+32u
// (u=0..2), r = t>>4 -> nodes r*4+v (v=0..3). 12 FFMA2 per k-step.
// x tile staged transposed in shared: xs[k][node], row stride 68 (16B aligned).
template<int K, bool FROM_GX>
__global__ __launch_bounds__(256) void gemm_fused(const float* __restrict__ xin,
                                                  const float* __restrict__ W,
                                                  const float* __restrict__ as_,
                                                  const float* __restrict__ ad_) {
    __shared__ float xs[K][68];
    int t  = threadIdx.x;
    int nb = blockIdx.x * 64;

    const float* xsrc = FROM_GX ? g_x : xin;
    for (int idx = t; idx < 64 * K; idx += 256) {
        int n = idx / K, k = idx - n * K;
        int gn = nb + n;
        xs[k][n] = (gn < N_NODES) ? xsrc[(size_t)gn * K + k] : 0.f;
    }
    __syncthreads();

    int c = t & 15;
    int r = t >> 4;

    unsigned long long acc[4][3];
#pragma unroll
    for (int v = 0; v < 4; v++)
#pragma unroll
        for (int u = 0; u < 3; u++) acc[v][u] = 0ull;

#pragma unroll 4
    for (int k = 0; k < K; k++) {
        float4 xv = *reinterpret_cast<const float4*>(&xs[k][r * 4]);
        const float* wr = W + (size_t)k * HID + 2 * c;
        unsigned long long w0 = __ldg((const unsigned long long*)(wr));
        unsigned long long w1 = __ldg((const unsigned long long*)(wr + 32));
        unsigned long long w2 = __ldg((const unsigned long long*)(wr + 64));
        unsigned long long x0 = pack2(xv.x, xv.x);
        unsigned long long x1 = pack2(xv.y, xv.y);
        unsigned long long x2 = pack2(xv.z, xv.z);
        unsigned long long x3 = pack2(xv.w, xv.w);
        acc[0][0] = fma2(x0, w0, acc[0][0]);
        acc[0][1] = fma2(x0, w1, acc[0][1]);
        acc[0][2] = fma2(x0, w2, acc[0][2]);
        acc[1][0] = fma2(x1, w0, acc[1][0]);
        acc[1][1] = fma2(x1, w1, acc[1][1]);
        acc[1][2] = fma2(x1, w2, acc[1][2]);
        acc[2][0] = fma2(x2, w0, acc[2][0]);
        acc[2][1] = fma2(x2, w1, acc[2][1]);
        acc[2][2] = fma2(x2, w2, acc[2][2]);
        acc[3][0] = fma2(x3, w0, acc[3][0]);
        acc[3][1] = fma2(x3, w1, acc[3][1]);
        acc[3][2] = fma2(x3, w2, acc[3][2]);
    }

    // attention vectors for this thread's 6 columns
    float as0, as1, as2, as3, as4, as5, ad0, ad1, ad2, ad3, ad4, ad5;
    {
        float2 a = __ldg((const float2*)(as_ + 2 * c));
        float2 b = __ldg((const float2*)(as_ + 2 * c + 32));
        float2 d = __ldg((const float2*)(as_ + 2 * c + 64));
        as0 = a.x; as1 = a.y; as2 = b.x; as3 = b.y; as4 = d.x; as5 = d.y;
        a = __ldg((const float2*)(ad_ + 2 * c));
        b = __ldg((const float2*)(ad_ + 2 * c + 32));
        d = __ldg((const float2*)(ad_ + 2 * c + 64));
        ad0 = a.x; ad1 = a.y; ad2 = b.x; ad3 = b.y; ad4 = d.x; ad5 = d.y;
    }

#pragma unroll
    for (int v = 0; v < 4; v++) {
        float h0, h1, h2, h3, h4, h5;
        unpack2(acc[v][0], h0, h1);
        unpack2(acc[v][1], h2, h3);
        unpack2(acc[v][2], h4, h5);
        int n = nb + r * 4 + v;
        if (n < N_NODES) {
            float* hr = g_h + (size_t)n * HID + 2 * c;
            *(float2*)(hr)      = make_float2(h0, h1);
            *(float2*)(hr + 32) = make_float2(h2, h3);
            *(float2*)(hr + 64) = make_float2(h4, h5);
        }
        float ps = h0 * as0 + h1 * as1 + h2 * as2 + h3 * as3 + h4 * as4 + h5 * as5;
        float pd = h0 * ad0 + h1 * ad1 + h2 * ad2 + h3 * ad3 + h4 * ad4 + h5 * ad5;
#pragma unroll
        for (int o = 8; o; o >>= 1) {
            ps += __shfl_down_sync(0xffffffffu, ps, o, 16);
            pd += __shfl_down_sync(0xffffffffu, pd, o, 16);
        }
        if (c == 0 && n < N_NODES) { g_es[n] = ps; g_ed[n] = pd; }
    }
}

// final layer gemm: out_dim = 1, warp per node
__global__ void gemm_logits_f(const float* __restrict__ W,
                              const float* __restrict__ as_,
                              const float* __restrict__ ad_) {
    int n = blockIdx.x * (blockDim.x >> 5) + (threadIdx.x >> 5);
    if (n >= N_NODES) return;
    int lane = threadIdx.x & 31;
    float acc = 0.f;
#pragma unroll
    for (int k = lane; k < HID; k += 32) acc += g_x[(size_t)n * HID + k] * __ldg(W + k);
#pragma unroll
    for (int o = 16; o; o >>= 1) acc += __shfl_down_sync(0xffffffffu, acc, o);
    if (lane == 0) {
        g_h[n]  = acc;
        g_es[n] = acc * __ldg(as_);
        g_ed[n] = acc * __ldg(ad_);
    }
}

// ---------------- fused attention + aggregation (wide layers) ----------------
// warp per dst node: segment-softmax + weighted gather, no atomics.
template<bool RESIDUAL>
__global__ void gat_fused96(const float* __restrict__ b) {
    int n = blockIdx.x * (blockDim.x >> 5) + (threadIdx.x >> 5);
    if (n >= N_NODES) return;
    int lane = threadIdx.x & 31;
    int beg = g_rp[n], end = g_rp[n + 1];
    float edv = g_ed[n];

    // pass A: segment max (lanes parallel over edges)
    float m = -1e30f;
    for (int i = beg + lane; i < end; i += 32)
        m = fmaxf(m, lrelu(g_es[g_csrc[i]] + edv));
#pragma unroll
    for (int o = 16; o; o >>= 1)
        m = fmaxf(m, __shfl_xor_sync(0xffffffffu, m, o));

    // pass B: s = sum(exp), num[j] = sum(exp * h[src][j]); unrolled x4 for MLP
    float s = 0.f, a0 = 0.f, a1 = 0.f, a2 = 0.f;
    int i = beg;
    for (; i + 4 <= end; i += 4) {
        int s0 = g_csrc[i], s1 = g_csrc[i + 1], s2 = g_csrc[i + 2], s3 = g_csrc[i + 3];
        float e0 = __expf(lrelu(g_es[s0] + edv) - m);
        float e1 = __expf(lrelu(g_es[s1] + edv) - m);
        float e2 = __expf(lrelu(g_es[s2] + edv) - m);
        float e3 = __expf(lrelu(g_es[s3] + edv) - m);
        const float* h0 = g_h + (size_t)s0 * HID;
        const float* h1 = g_h + (size_t)s1 * HID;
        const float* h2 = g_h + (size_t)s2 * HID;
        const float* h3 = g_h + (size_t)s3 * HID;
        float x00 = h0[lane], x01 = h0[lane + 32], x02 = h0[lane + 64];
        float x10 = h1[lane], x11 = h1[lane + 32], x12 = h1[lane + 64];
        float x20 = h2[lane], x21 = h2[lane + 32], x22 = h2[lane + 64];
        float x30 = h3[lane], x31 = h3[lane + 32], x32 = h3[lane + 64];
        s += (e0 + e1) + (e2 + e3);
        a0 = fmaf(e0, x00, a0); a1 = fmaf(e0, x01, a1); a2 = fmaf(e0, x02, a2);
        a0 = fmaf(e1, x10, a0); a1 = fmaf(e1, x11, a1); a2 = fmaf(e1, x12, a2);
        a0 = fmaf(e2, x20, a0); a1 = fmaf(e2, x21, a1); a2 = fmaf(e2, x22, a2);
        a0 = fmaf(e3, x30, a0); a1 = fmaf(e3, x31, a1); a2 = fmaf(e3, x32, a2);
    }
    for (; i < end; i++) {
        int s0 = g_csrc[i];
        float e0 = __expf(lrelu(g_es[s0] + edv) - m);
        const float* h0 = g_h + (size_t)s0 * HID;
        s += e0;
        a0 = fmaf(e0, h0[lane], a0);
        a1 = fmaf(e0, h0[lane + 32], a1);
        a2 = fmaf(e0, h0[lane + 64], a2);
    }
    float inv = 1.f / s;
    float* xr = g_x + (size_t)n * HID;
    float v0 = a0 * inv + __ldg(b + lane);
    float v1 = a1 * inv + __ldg(b + lane + 32);
    float v2 = a2 * inv + __ldg(b + lane + 64);
    if (RESIDUAL) { v0 += xr[lane]; v1 += xr[lane + 32]; v2 += xr[lane + 64]; }
    xr[lane]      = fmaxf(v0, 0.f);
    xr[lane + 32] = fmaxf(v1, 0.f);
    xr[lane + 64] = fmaxf(v2, 0.f);
}

// final layer: out_dim = 1, lanes parallel over edges
__global__ void gat_fused1(const float* __restrict__ b, float* __restrict__ dout) {
    int n = blockIdx.x * (blockDim.x >> 5) + (threadIdx.x >> 5);
    if (n >= N_NODES) return;
    int lane = threadIdx.x & 31;
    int beg = g_rp[n], end = g_rp[n + 1];
    float edv = g_ed[n];

    float m = -1e30f;
    for (int i = beg + lane; i < end; i += 32)
        m = fmaxf(m, lrelu(g_es[g_csrc[i]] + edv));
#pragma unroll
    for (int o = 16; o; o >>= 1)
        m = fmaxf(m, __shfl_xor_sync(0xffffffffu, m, o));

    float s = 0.f, num = 0.f;
    for (int i = beg + lane; i < end; i += 32) {
        int src = g_csrc[i];
        float ex = __expf(lrelu(g_es[src] + edv) - m);
        s += ex;
        num = fmaf(ex, g_h[src], num);
    }
#pragma unroll
    for (int o = 16; o; o >>= 1) {
        s   += __shfl_xor_sync(0xffffffffu, s, o);
        num += __shfl_xor_sync(0xffffffffu, num, o);
    }
    if (lane == 0) dout[n] = num / s + __ldg(b);
}

// ---------------- launch ----------------
extern "C" void kernel_launch(void* const* d_in, const int* in_sizes, int n_in,
                              void* d_out, int out_size) {
    const float* x  = (const float*)d_in[0];
    const int*   ei = (const int*)d_in[1];   // int32 [2, E]
    // d_in[2] = edge_weight (ignored, matches reference)
    const float* W0 = (const float*)d_in[3];
    const float* as0 = (const float*)d_in[4];
    const float* ad0 = (const float*)d_in[5];
    const float* b0 = (const float*)d_in[6];
    const float* W1 = (const float*)d_in[7];
    const float* as1 = (const float*)d_in[8];
    const float* ad1 = (const float*)d_in[9];
    const float* b1 = (const float*)d_in[10];
    const float* W2 = (const float*)d_in[11];
    const float* as2 = (const float*)d_in[12];
    const float* ad2 = (const float*)d_in[13];
    const float* b2 = (const float*)d_in[14];
    const float* Wf = (const float*)d_in[15];
    const float* asf = (const float*)d_in[16];
    const float* adf = (const float*)d_in[17];
    const float* bf = (const float*)d_in[18];
    float* dout = (float*)d_out;

    const int EB = 256;
    const int EGRID = (E_TOT + EB - 1) / EB;                 // thread-per-edge
    const int WGRID = (N_NODES + (EB / 32) - 1) / (EB / 32); // warp-per-node
    const int ZGRID = (N_NODES + EB - 1) / EB;
    const int GGRID = (N_NODES + 63) / 64;                   // 64 nodes per gemm block

    // ---- CSR build (once; edges identical for all layers) ----
    csr_zero<<<ZGRID, EB>>>();
    csr_hist<<<EGRID, EB>>>(ei);
    csr_scan<<<1, 1024>>>();
    csr_scatter<<<EGRID, EB>>>(ei);

    // ---- layer 0 (in=32, no residual) ----
    gemm_fused<32, false><<<GGRID, 256>>>(x, W0, as0, ad0);
    gat_fused96<false><<<WGRID, EB>>>(b0);

    // ---- layer 1 (in=96, residual) ----
    gemm_fused<96, true><<<GGRID, 256>>>(nullptr, W1, as1, ad1);
    gat_fused96<true><<<WGRID, EB>>>(b1);

    // ---- layer 2 (in=96, residual) ----
    gemm_fused<96, true><<<GGRID, 256>>>(nullptr, W2, as2, ad2);
    gat_fused96<true><<<WGRID, EB>>>(b2);

    // ---- final layer (out=1) ----
    gemm_logits_f<<<WGRID, EB>>>(Wf, asf, adf);
    gat_fused1<<<WGRID, EB>>>(bf, dout);
}

// round 8
// speedup vs baseline: 2.2525x; 1.0183x over previous
#include <cuda_runtime.h>
#include <cstdint>

#define N_NODES 50000
#define N_EDGES 800000
#define E_TOT   (N_EDGES + N_NODES)   // self loops appended
#define HID     96
#define NEG_SLOPE 0.2f

// ---------------- scratch (allocation-free: device globals) ----------------
__device__ float g_x[N_NODES * HID];   // current layer input features
__device__ float g_h[N_NODES * HID];   // h = x @ W ([N] for final layer)
__device__ float g_es[N_NODES];
__device__ float g_ed[N_NODES];
// CSR (rebuilt every launch; edges are launch-invariant inputs)
__device__ int g_cnt[N_NODES];
__device__ int g_rp [N_NODES + 1];
__device__ int g_cur[N_NODES];
__device__ int g_csrc[E_TOT];

__device__ __forceinline__ float lrelu(float e) {
    return (e > 0.f) ? e : NEG_SLOPE * e;
}

// packed f32x2 helpers (FFMA2 is PTX-only on sm_103a)
__device__ __forceinline__ unsigned long long pack2(float lo, float hi) {
    unsigned long long r;
    asm("mov.b64 %0, {%1, %2};" : "=l"(r) : "f"(lo), "f"(hi));
    return r;
}
__device__ __forceinline__ void unpack2(unsigned long long v, float& lo, float& hi) {
    asm("mov.b64 {%0, %1}, %2;" : "=f"(lo), "=f"(hi) : "l"(v));
}
__device__ __forceinline__ unsigned long long fma2(unsigned long long a,
                                                   unsigned long long b,
                                                   unsigned long long c) {
    unsigned long long d;
    asm("fma.rn.f32x2 %0, %1, %2, %3;" : "=l"(d) : "l"(a), "l"(b), "l"(c));
    return d;
}

// ---------------- CSR build ----------------
__global__ void csr_zero() {
    int i = blockIdx.x * blockDim.x + threadIdx.x;
    if (i < N_NODES) g_cnt[i] = 0;
}

// 4 edges per thread for MLP
__global__ void csr_hist(const int* __restrict__ ei) {
    int base = (blockIdx.x * blockDim.x + threadIdx.x) * 4;
    int d[4];
#pragma unroll
    for (int u = 0; u < 4; u++) {
        int i = base + u;
        d[u] = (i < E_TOT) ? ((i < N_EDGES) ? __ldg(ei + N_EDGES + i) : (i - N_EDGES)) : -1;
    }
#pragma unroll
    for (int u = 0; u < 4; u++)
        if (d[u] >= 0) atomicAdd(&g_cnt[d[u]], 1);
}

// single-block exclusive scan of g_cnt -> g_rp, g_cur
__global__ void csr_scan() {
    __shared__ int part[1024];
    const int CH = (N_NODES + 1023) / 1024;   // 49
    int t = threadIdx.x;
    int base = t * CH;
    int sum = 0;
    for (int c = 0; c < CH; c++) {
        int idx = base + c;
        if (idx < N_NODES) sum += g_cnt[idx];
    }
    part[t] = sum;
    __syncthreads();
    for (int off = 1; off < 1024; off <<= 1) {
        int v = (t >= off) ? part[t - off] : 0;
        __syncthreads();
        if (t >= off) part[t] += v;
        __syncthreads();
    }
    int run = (t > 0) ? part[t - 1] : 0;
    for (int c = 0; c < CH; c++) {
        int idx = base + c;
        if (idx < N_NODES) {
            g_rp[idx]  = run;
            g_cur[idx] = run;
            run += g_cnt[idx];
        }
    }
    if (t == 1023) g_rp[N_NODES] = E_TOT;
}

// 4 edges per thread for MLP
__global__ void csr_scatter(const int* __restrict__ ei) {
    int base = (blockIdx.x * blockDim.x + threadIdx.x) * 4;
    int s[4], d[4];
#pragma unroll
    for (int u = 0; u < 4; u++) {
        int i = base + u;
        if (i < N_EDGES)     { s[u] = __ldg(ei + i); d[u] = __ldg(ei + N_EDGES + i); }
        else if (i < E_TOT)  { s[u] = d[u] = i - N_EDGES; }
        else                 { d[u] = -1; }
    }
#pragma unroll
    for (int u = 0; u < 4; u++) {
        if (d[u] >= 0) {
            int pos = atomicAdd(&g_cur[d[u]], 1);
            g_csrc[pos] = s[u];
        }
    }
}

// ---------------- GEMM + fused logits: h = x@W, es = h.as, ed = h.ad --------
// 256 threads, 64 nodes/block. Thread t: c = t&15 -> col pairs {2c,2c+1}+32u
// (u=0..2), r = t>>4 -> nodes r*4+v (v=0..3). 12 FFMA2 per k-step.
template<int K, bool FROM_GX>
__global__ __launch_bounds__(256) void gemm_fused(const float* __restrict__ xin,
                                                  const float* __restrict__ W,
                                                  const float* __restrict__ as_,
                                                  const float* __restrict__ ad_) {
    __shared__ float xs[K][68];
    int t  = threadIdx.x;
    int nb = blockIdx.x * 64;

    const float* xsrc = FROM_GX ? g_x : xin;
    for (int idx = t; idx < 64 * K; idx += 256) {
        int n = idx / K, k = idx - n * K;
        int gn = nb + n;
        xs[k][n] = (gn < N_NODES) ? xsrc[(size_t)gn * K + k] : 0.f;
    }
    __syncthreads();

    int c = t & 15;
    int r = t >> 4;

    unsigned long long acc[4][3];
#pragma unroll
    for (int v = 0; v < 4; v++)
#pragma unroll
        for (int u = 0; u < 3; u++) acc[v][u] = 0ull;

#pragma unroll 4
    for (int k = 0; k < K; k++) {
        float4 xv = *reinterpret_cast<const float4*>(&xs[k][r * 4]);
        const float* wr = W + (size_t)k * HID + 2 * c;
        unsigned long long w0 = __ldg((const unsigned long long*)(wr));
        unsigned long long w1 = __ldg((const unsigned long long*)(wr + 32));
        unsigned long long w2 = __ldg((const unsigned long long*)(wr + 64));
        unsigned long long x0 = pack2(xv.x, xv.x);
        unsigned long long x1 = pack2(xv.y, xv.y);
        unsigned long long x2 = pack2(xv.z, xv.z);
        unsigned long long x3 = pack2(xv.w, xv.w);
        acc[0][0] = fma2(x0, w0, acc[0][0]);
        acc[0][1] = fma2(x0, w1, acc[0][1]);
        acc[0][2] = fma2(x0, w2, acc[0][2]);
        acc[1][0] = fma2(x1, w0, acc[1][0]);
        acc[1][1] = fma2(x1, w1, acc[1][1]);
        acc[1][2] = fma2(x1, w2, acc[1][2]);
        acc[2][0] = fma2(x2, w0, acc[2][0]);
        acc[2][1] = fma2(x2, w1, acc[2][1]);
        acc[2][2] = fma2(x2, w2, acc[2][2]);
        acc[3][0] = fma2(x3, w0, acc[3][0]);
        acc[3][1] = fma2(x3, w1, acc[3][1]);
        acc[3][2] = fma2(x3, w2, acc[3][2]);
    }

    float as0, as1, as2, as3, as4, as5, ad0, ad1, ad2, ad3, ad4, ad5;
    {
        float2 a = __ldg((const float2*)(as_ + 2 * c));
        float2 b = __ldg((const float2*)(as_ + 2 * c + 32));
        float2 d = __ldg((const float2*)(as_ + 2 * c + 64));
        as0 = a.x; as1 = a.y; as2 = b.x; as3 = b.y; as4 = d.x; as5 = d.y;
        a = __ldg((const float2*)(ad_ + 2 * c));
        b = __ldg((const float2*)(ad_ + 2 * c + 32));
        d = __ldg((const float2*)(ad_ + 2 * c + 64));
        ad0 = a.x; ad1 = a.y; ad2 = b.x; ad3 = b.y; ad4 = d.x; ad5 = d.y;
    }

#pragma unroll
    for (int v = 0; v < 4; v++) {
        float h0, h1, h2, h3, h4, h5;
        unpack2(acc[v][0], h0, h1);
        unpack2(acc[v][1], h2, h3);
        unpack2(acc[v][2], h4, h5);
        int n = nb + r * 4 + v;
        if (n < N_NODES) {
            float* hr = g_h + (size_t)n * HID + 2 * c;
            *(float2*)(hr)      = make_float2(h0, h1);
            *(float2*)(hr + 32) = make_float2(h2, h3);
            *(float2*)(hr + 64) = make_float2(h4, h5);
        }
        float ps = h0 * as0 + h1 * as1 + h2 * as2 + h3 * as3 + h4 * as4 + h5 * as5;
        float pd = h0 * ad0 + h1 * ad1 + h2 * ad2 + h3 * ad3 + h4 * ad4 + h5 * ad5;
#pragma unroll
        for (int o = 8; o; o >>= 1) {
            ps += __shfl_down_sync(0xffffffffu, ps, o, 16);
            pd += __shfl_down_sync(0xffffffffu, pd, o, 16);
        }
        if (c == 0 && n < N_NODES) { g_es[n] = ps; g_ed[n] = pd; }
    }
}

// final layer gemm: out_dim = 1, warp per node
__global__ void gemm_logits_f(const float* __restrict__ W,
                              const float* __restrict__ as_,
                              const float* __restrict__ ad_) {
    int n = blockIdx.x * (blockDim.x >> 5) + (threadIdx.x >> 5);
    if (n >= N_NODES) return;
    int lane = threadIdx.x & 31;
    float acc = 0.f;
#pragma unroll
    for (int k = lane; k < HID; k += 32) acc += g_x[(size_t)n * HID + k] * __ldg(W + k);
#pragma unroll
    for (int o = 16; o; o >>= 1) acc += __shfl_down_sync(0xffffffffu, acc, o);
    if (lane == 0) {
        g_h[n]  = acc;
        g_es[n] = acc * __ldg(as_);
        g_ed[n] = acc * __ldg(ad_);
    }
}

// ---------------- fused attention + aggregation (wide layers) ----------------
// Warp per dst node. Chunk-of-32 edge processing with online softmax:
// lanes load csrc (coalesced) + es (gather) in parallel once per chunk,
// inner loop broadcasts (e, src) by shuffle -> h gathers depend on shfl only.
template<bool RESIDUAL>
__global__ void gat_fused96(const float* __restrict__ b) {
    int n = blockIdx.x * (blockDim.x >> 5) + (threadIdx.x >> 5);
    if (n >= N_NODES) return;
    int lane = threadIdx.x & 31;
    int beg = g_rp[n], end = g_rp[n + 1];
    float edv = g_ed[n];

    float m = -1e30f;
    float s = 0.f, a0 = 0.f, a1 = 0.f, a2 = 0.f;

    for (int cb = beg; cb < end; cb += 32) {
        int nedge = min(32, end - cb);
        int ii = cb + lane;
        int srcl = (ii < end) ? g_csrc[ii] : 0;
        float el = (ii < end) ? lrelu(g_es[srcl] + edv) : -1e30f;

        // chunk max
        float mc = el;
#pragma unroll
        for (int o = 16; o; o >>= 1)
            mc = fmaxf(mc, __shfl_xor_sync(0xffffffffu, mc, o));
        float mn = fmaxf(m, mc);
        float scale = __expf(m - mn);   // first chunk: exp(-huge) = 0
        s *= scale; a0 *= scale; a1 *= scale; a2 *= scale;
        m = mn;

#pragma unroll 4
        for (int j = 0; j < nedge; j++) {
            float ej = __shfl_sync(0xffffffffu, el,   j);
            int   sj = __shfl_sync(0xffffffffu, srcl, j);
            float ex = __expf(ej - m);
            const float* h = g_h + (size_t)sj * HID;
            s += ex;
            a0 = fmaf(ex, h[lane],      a0);
            a1 = fmaf(ex, h[lane + 32], a1);
            a2 = fmaf(ex, h[lane + 64], a2);
        }
    }

    float inv = 1.f / s;
    float* xr = g_x + (size_t)n * HID;
    float v0 = a0 * inv + __ldg(b + lane);
    float v1 = a1 * inv + __ldg(b + lane + 32);
    float v2 = a2 * inv + __ldg(b + lane + 64);
    if (RESIDUAL) { v0 += xr[lane]; v1 += xr[lane + 32]; v2 += xr[lane + 64]; }
    xr[lane]      = fmaxf(v0, 0.f);
    xr[lane + 32] = fmaxf(v1, 0.f);
    xr[lane + 64] = fmaxf(v2, 0.f);
}

// final layer: out_dim = 1, lanes parallel over edges
__global__ void gat_fused1(const float* __restrict__ b, float* __restrict__ dout) {
    int n = blockIdx.x * (blockDim.x >> 5) + (threadIdx.x >> 5);
    if (n >= N_NODES) return;
    int lane = threadIdx.x & 31;
    int beg = g_rp[n], end = g_rp[n + 1];
    float edv = g_ed[n];

    float m = -1e30f;
    for (int i = beg + lane; i < end; i += 32)
        m = fmaxf(m, lrelu(g_es[g_csrc[i]] + edv));
#pragma unroll
    for (int o = 16; o; o >>= 1)
        m = fmaxf(m, __shfl_xor_sync(0xffffffffu, m, o));

    float s = 0.f, num = 0.f;
    for (int i = beg + lane; i < end; i += 32) {
        int src = g_csrc[i];
        float ex = __expf(lrelu(g_es[src] + edv) - m);
        s += ex;
        num = fmaf(ex, g_h[src], num);
    }
#pragma unroll
    for (int o = 16; o; o >>= 1) {
        s   += __shfl_xor_sync(0xffffffffu, s, o);
        num += __shfl_xor_sync(0xffffffffu, num, o);
    }
    if (lane == 0) dout[n] = num / s + __ldg(b);
}

// ---------------- launch ----------------
extern "C" void kernel_launch(void* const* d_in, const int* in_sizes, int n_in,
                              void* d_out, int out_size) {
    const float* x  = (const float*)d_in[0];
    const int*   ei = (const int*)d_in[1];   // int32 [2, E]
    // d_in[2] = edge_weight (ignored, matches reference)
    const float* W0 = (const float*)d_in[3];
    const float* as0 = (const float*)d_in[4];
    const float* ad0 = (const float*)d_in[5];
    const float* b0 = (const float*)d_in[6];
    const float* W1 = (const float*)d_in[7];
    const float* as1 = (const float*)d_in[8];
    const float* ad1 = (const float*)d_in[9];
    const float* b1 = (const float*)d_in[10];
    const float* W2 = (const float*)d_in[11];
    const float* as2 = (const float*)d_in[12];
    const float* ad2 = (const float*)d_in[13];
    const float* b2 = (const float*)d_in[14];
    const float* Wf = (const float*)d_in[15];
    const float* asf = (const float*)d_in[16];
    const float* adf = (const float*)d_in[17];
    const float* bf = (const float*)d_in[18];
    float* dout = (float*)d_out;

    const int EB = 256;
    const int E4GRID = (E_TOT + EB * 4 - 1) / (EB * 4);      // 4 edges/thread
    const int WGRID  = (N_NODES + (EB / 32) - 1) / (EB / 32); // warp-per-node
    const int ZGRID  = (N_NODES + EB - 1) / EB;
    const int GGRID  = (N_NODES + 63) / 64;                   // 64 nodes per gemm block

    // ---- CSR build (once; edges identical for all layers) ----
    csr_zero<<<ZGRID, EB>>>();
    csr_hist<<<E4GRID, EB>>>(ei);
    csr_scan<<<1, 1024>>>();
    csr_scatter<<<E4GRID, EB>>>(ei);

    // ---- layer 0 (in=32, no residual) ----
    gemm_fused<32, false><<<GGRID, 256>>>(x, W0, as0, ad0);
    gat_fused96<false><<<WGRID, EB>>>(b0);

    // ---- layer 1 (in=96, residual) ----
    gemm_fused<96, true><<<GGRID, 256>>>(nullptr, W1, as1, ad1);
    gat_fused96<true><<<WGRID, EB>>>(b1);

    // ---- layer 2 (in=96, residual) ----
    gemm_fused<96, true><<<GGRID, 256>>>(nullptr, W2, as2, ad2);
    gat_fused96<true><<<WGRID, EB>>>(b2);

    // ---- final layer (out=1) ----
    gemm_logits_f<<<WGRID, EB>>>(Wf, asf, adf);
    gat_fused1<<<WGRID, EB>>>(bf, dout);
}

// round 9
// speedup vs baseline: 2.2590x; 1.0029x over previous
#include <cuda_runtime.h>
#include <cstdint>

#define N_NODES 50000
#define N_EDGES 800000
#define E_TOT   (N_EDGES + N_NODES)   // self loops appended
#define HID     96
#define NEG_SLOPE 0.2f

// ---------------- scratch (allocation-free: device globals) ----------------
__device__ float g_x[N_NODES * HID];   // current layer input features
__device__ float g_h[N_NODES * HID];   // h = x @ W ([N] for final layer)
__device__ float g_es[N_NODES];
__device__ float g_ed[N_NODES];
// CSR (rebuilt every launch; edges are launch-invariant inputs)
__device__ int g_cnt[N_NODES];
__device__ int g_rp [N_NODES + 1];
__device__ int g_cur[N_NODES];
__device__ int g_csrc[E_TOT];

__device__ __forceinline__ float lrelu(float e) {
    return (e > 0.f) ? e : NEG_SLOPE * e;
}

// packed f32x2 helpers (FFMA2 is PTX-only on sm_103a)
__device__ __forceinline__ unsigned long long pack2(float lo, float hi) {
    unsigned long long r;
    asm("mov.b64 %0, {%1, %2};" : "=l"(r) : "f"(lo), "f"(hi));
    return r;
}
__device__ __forceinline__ void unpack2(unsigned long long v, float& lo, float& hi) {
    asm("mov.b64 {%0, %1}, %2;" : "=f"(lo), "=f"(hi) : "l"(v));
}
__device__ __forceinline__ unsigned long long fma2(unsigned long long a,
                                                   unsigned long long b,
                                                   unsigned long long c) {
    unsigned long long d;
    asm("fma.rn.f32x2 %0, %1, %2, %3;" : "=l"(d) : "l"(a), "l"(b), "l"(c));
    return d;
}

// ---------------- CSR build ----------------
__global__ void csr_zero() {
    int i = blockIdx.x * blockDim.x + threadIdx.x;
    if (i < N_NODES) g_cnt[i] = 0;
}

// 4 edges per thread for MLP
__global__ void csr_hist(const int* __restrict__ ei) {
    int base = (blockIdx.x * blockDim.x + threadIdx.x) * 4;
    int d[4];
#pragma unroll
    for (int u = 0; u < 4; u++) {
        int i = base + u;
        d[u] = (i < E_TOT) ? ((i < N_EDGES) ? __ldg(ei + N_EDGES + i) : (i - N_EDGES)) : -1;
    }
#pragma unroll
    for (int u = 0; u < 4; u++)
        if (d[u] >= 0) atomicAdd(&g_cnt[d[u]], 1);
}

// single-block exclusive scan of g_cnt -> g_rp, g_cur
__global__ void csr_scan() {
    __shared__ int part[1024];
    const int CH = (N_NODES + 1023) / 1024;   // 49
    int t = threadIdx.x;
    int base = t * CH;
    int sum = 0;
    for (int c = 0; c < CH; c++) {
        int idx = base + c;
        if (idx < N_NODES) sum += g_cnt[idx];
    }
    part[t] = sum;
    __syncthreads();
    for (int off = 1; off < 1024; off <<= 1) {
        int v = (t >= off) ? part[t - off] : 0;
        __syncthreads();
        if (t >= off) part[t] += v;
        __syncthreads();
    }
    int run = (t > 0) ? part[t - 1] : 0;
    for (int c = 0; c < CH; c++) {
        int idx = base + c;
        if (idx < N_NODES) {
            g_rp[idx]  = run;
            g_cur[idx] = run;
            run += g_cnt[idx];
        }
    }
    if (t == 1023) g_rp[N_NODES] = E_TOT;
}

// 4 edges per thread for MLP
__global__ void csr_scatter(const int* __restrict__ ei) {
    int base = (blockIdx.x * blockDim.x + threadIdx.x) * 4;
    int s[4], d[4];
#pragma unroll
    for (int u = 0; u < 4; u++) {
        int i = base + u;
        if (i < N_EDGES)     { s[u] = __ldg(ei + i); d[u] = __ldg(ei + N_EDGES + i); }
        else if (i < E_TOT)  { s[u] = d[u] = i - N_EDGES; }
        else                 { d[u] = -1; }
    }
#pragma unroll
    for (int u = 0; u < 4; u++) {
        if (d[u] >= 0) {
            int pos = atomicAdd(&g_cur[d[u]], 1);
            g_csrc[pos] = s[u];
        }
    }
}

// ---------------- GEMM + fused logits: h = x@W, es = h.as, ed = h.ad --------
// 256 threads, 64 nodes/block. Thread t: c = t&15 -> col pairs {2c,2c+1}+32u
// (u=0..2), r = t>>4 -> nodes r*4+v (v=0..3). 12 FFMA2 per k-step.
template<int K, bool FROM_GX>
__global__ __launch_bounds__(256) void gemm_fused(const float* __restrict__ xin,
                                                  const float* __restrict__ W,
                                                  const float* __restrict__ as_,
                                                  const float* __restrict__ ad_) {
    __shared__ float xs[K][68];
    int t  = threadIdx.x;
    int nb = blockIdx.x * 64;

    const float* xsrc = FROM_GX ? g_x : xin;
    for (int idx = t; idx < 64 * K; idx += 256) {
        int n = idx / K, k = idx - n * K;
        int gn = nb + n;
        xs[k][n] = (gn < N_NODES) ? xsrc[(size_t)gn * K + k] : 0.f;
    }
    __syncthreads();

    int c = t & 15;
    int r = t >> 4;

    unsigned long long acc[4][3];
#pragma unroll
    for (int v = 0; v < 4; v++)
#pragma unroll
        for (int u = 0; u < 3; u++) acc[v][u] = 0ull;

#pragma unroll 4
    for (int k = 0; k < K; k++) {
        float4 xv = *reinterpret_cast<const float4*>(&xs[k][r * 4]);
        const float* wr = W + (size_t)k * HID + 2 * c;
        unsigned long long w0 = __ldg((const unsigned long long*)(wr));
        unsigned long long w1 = __ldg((const unsigned long long*)(wr + 32));
        unsigned long long w2 = __ldg((const unsigned long long*)(wr + 64));
        unsigned long long x0 = pack2(xv.x, xv.x);
        unsigned long long x1 = pack2(xv.y, xv.y);
        unsigned long long x2 = pack2(xv.z, xv.z);
        unsigned long long x3 = pack2(xv.w, xv.w);
        acc[0][0] = fma2(x0, w0, acc[0][0]);
        acc[0][1] = fma2(x0, w1, acc[0][1]);
        acc[0][2] = fma2(x0, w2, acc[0][2]);
        acc[1][0] = fma2(x1, w0, acc[1][0]);
        acc[1][1] = fma2(x1, w1, acc[1][1]);
        acc[1][2] = fma2(x1, w2, acc[1][2]);
        acc[2][0] = fma2(x2, w0, acc[2][0]);
        acc[2][1] = fma2(x2, w1, acc[2][1]);
        acc[2][2] = fma2(x2, w2, acc[2][2]);
        acc[3][0] = fma2(x3, w0, acc[3][0]);
        acc[3][1] = fma2(x3, w1, acc[3][1]);
        acc[3][2] = fma2(x3, w2, acc[3][2]);
    }

    float as0, as1, as2, as3, as4, as5, ad0, ad1, ad2, ad3, ad4, ad5;
    {
        float2 a = __ldg((const float2*)(as_ + 2 * c));
        float2 b = __ldg((const float2*)(as_ + 2 * c + 32));
        float2 d = __ldg((const float2*)(as_ + 2 * c + 64));
        as0 = a.x; as1 = a.y; as2 = b.x; as3 = b.y; as4 = d.x; as5 = d.y;
        a = __ldg((const float2*)(ad_ + 2 * c));
        b = __ldg((const float2*)(ad_ + 2 * c + 32));
        d = __ldg((const float2*)(ad_ + 2 * c + 64));
        ad0 = a.x; ad1 = a.y; ad2 = b.x; ad3 = b.y; ad4 = d.x; ad5 = d.y;
    }

#pragma unroll
    for (int v = 0; v < 4; v++) {
        float h0, h1, h2, h3, h4, h5;
        unpack2(acc[v][0], h0, h1);
        unpack2(acc[v][1], h2, h3);
        unpack2(acc[v][2], h4, h5);
        int n = nb + r * 4 + v;
        if (n < N_NODES) {
            float* hr = g_h + (size_t)n * HID + 2 * c;
            *(float2*)(hr)      = make_float2(h0, h1);
            *(float2*)(hr + 32) = make_float2(h2, h3);
            *(float2*)(hr + 64) = make_float2(h4, h5);
        }
        float ps = h0 * as0 + h1 * as1 + h2 * as2 + h3 * as3 + h4 * as4 + h5 * as5;
        float pd = h0 * ad0 + h1 * ad1 + h2 * ad2 + h3 * ad3 + h4 * ad4 + h5 * ad5;
#pragma unroll
        for (int o = 8; o; o >>= 1) {
            ps += __shfl_down_sync(0xffffffffu, ps, o, 16);
            pd += __shfl_down_sync(0xffffffffu, pd, o, 16);
        }
        if (c == 0 && n < N_NODES) { g_es[n] = ps; g_ed[n] = pd; }
    }
}

// final layer gemm: out_dim = 1, warp per node
__global__ void gemm_logits_f(const float* __restrict__ W,
                              const float* __restrict__ as_,
                              const float* __restrict__ ad_) {
    int n = blockIdx.x * (blockDim.x >> 5) + (threadIdx.x >> 5);
    if (n >= N_NODES) return;
    int lane = threadIdx.x & 31;
    float acc = 0.f;
#pragma unroll
    for (int k = lane; k < HID; k += 32) acc += g_x[(size_t)n * HID + k] * __ldg(W + k);
#pragma unroll
    for (int o = 16; o; o >>= 1) acc += __shfl_down_sync(0xffffffffu, acc, o);
    if (lane == 0) {
        g_h[n]  = acc;
        g_es[n] = acc * __ldg(as_);
        g_ed[n] = acc * __ldg(ad_);
    }
}

// ---------------- fused attention + aggregation (wide layers) ----------------
// Warp per dst node. Chunk-of-32 edge processing with online softmax:
// lanes load csrc (coalesced) + es (gather) in parallel once per chunk,
// inner loop broadcasts (e, src) by shuffle -> h gathers depend on shfl only.
template<bool RESIDUAL>
__global__ void gat_fused96(const float* __restrict__ b) {
    int n = blockIdx.x * (blockDim.x >> 5) + (threadIdx.x >> 5);
    if (n >= N_NODES) return;
    int lane = threadIdx.x & 31;
    int beg = g_rp[n], end = g_rp[n + 1];
    float edv = g_ed[n];

    float m = -1e30f;
    float s = 0.f, a0 = 0.f, a1 = 0.f, a2 = 0.f;

    for (int cb = beg; cb < end; cb += 32) {
        int nedge = min(32, end - cb);
        int ii = cb + lane;
        int srcl = (ii < end) ? g_csrc[ii] : 0;
        float el = (ii < end) ? lrelu(g_es[srcl] + edv) : -1e30f;

        // chunk max
        float mc = el;
#pragma unroll
        for (int o = 16; o; o >>= 1)
            mc = fmaxf(mc, __shfl_xor_sync(0xffffffffu, mc, o));
        float mn = fmaxf(m, mc);
        float scale = __expf(m - mn);   // first chunk: exp(-huge) = 0
        s *= scale; a0 *= scale; a1 *= scale; a2 *= scale;
        m = mn;

#pragma unroll 4
        for (int j = 0; j < nedge; j++) {
            float ej = __shfl_sync(0xffffffffu, el,   j);
            int   sj = __shfl_sync(0xffffffffu, srcl, j);
            float ex = __expf(ej - m);
            const float* h = g_h + (size_t)sj * HID;
            s += ex;
            a0 = fmaf(ex, h[lane],      a0);
            a1 = fmaf(ex, h[lane + 32], a1);
            a2 = fmaf(ex, h[lane + 64], a2);
        }
    }

    float inv = 1.f / s;
    float* xr = g_x + (size_t)n * HID;
    float v0 = a0 * inv + __ldg(b + lane);
    float v1 = a1 * inv + __ldg(b + lane + 32);
    float v2 = a2 * inv + __ldg(b + lane + 64);
    if (RESIDUAL) { v0 += xr[lane]; v1 += xr[lane + 32]; v2 += xr[lane + 64]; }
    xr[lane]      = fmaxf(v0, 0.f);
    xr[lane + 32] = fmaxf(v1, 0.f);
    xr[lane + 64] = fmaxf(v2, 0.f);
}

// final layer: out_dim = 1, lanes parallel over edges
__global__ void gat_fused1(const float* __restrict__ b, float* __restrict__ dout) {
    int n = blockIdx.x * (blockDim.x >> 5) + (threadIdx.x >> 5);
    if (n >= N_NODES) return;
    int lane = threadIdx.x & 31;
    int beg = g_rp[n], end = g_rp[n + 1];
    float edv = g_ed[n];

    float m = -1e30f;
    for (int i = beg + lane; i < end; i += 32)
        m = fmaxf(m, lrelu(g_es[g_csrc[i]] + edv));
#pragma unroll
    for (int o = 16; o; o >>= 1)
        m = fmaxf(m, __shfl_xor_sync(0xffffffffu, m, o));

    float s = 0.f, num = 0.f;
    for (int i = beg + lane; i < end; i += 32) {
        int src = g_csrc[i];
        float ex = __expf(lrelu(g_es[src] + edv) - m);
        s += ex;
        num = fmaf(ex, g_h[src], num);
    }
#pragma unroll
    for (int o = 16; o; o >>= 1) {
        s   += __shfl_xor_sync(0xffffffffu, s, o);
        num += __shfl_xor_sync(0xffffffffu, num, o);
    }
    if (lane == 0) dout[n] = num / s + __ldg(b);
}

// ---------------- launch ----------------
extern "C" void kernel_launch(void* const* d_in, const int* in_sizes, int n_in,
                              void* d_out, int out_size) {
    const float* x  = (const float*)d_in[0];
    const int*   ei = (const int*)d_in[1];   // int32 [2, E]
    // d_in[2] = edge_weight (ignored, matches reference)
    const float* W0 = (const float*)d_in[3];
    const float* as0 = (const float*)d_in[4];
    const float* ad0 = (const float*)d_in[5];
    const float* b0 = (const float*)d_in[6];
    const float* W1 = (const float*)d_in[7];
    const float* as1 = (const float*)d_in[8];
    const float* ad1 = (const float*)d_in[9];
    const float* b1 = (const float*)d_in[10];
    const float* W2 = (const float*)d_in[11];
    const float* as2 = (const float*)d_in[12];
    const float* ad2 = (const float*)d_in[13];
    const float* b2 = (const float*)d_in[14];
    const float* Wf = (const float*)d_in[15];
    const float* asf = (const float*)d_in[16];
    const float* adf = (const float*)d_in[17];
    const float* bf = (const float*)d_in[18];
    float* dout = (float*)d_out;

    const int EB = 256;
    const int E4GRID = (E_TOT + EB * 4 - 1) / (EB * 4);      // 4 edges/thread
    const int WGRID  = (N_NODES + (EB / 32) - 1) / (EB / 32); // warp-per-node
    const int ZGRID  = (N_NODES + EB - 1) / EB;
    const int GGRID  = (N_NODES + 63) / 64;                   // 64 nodes per gemm block

    // ---- CSR build (once; edges identical for all layers) ----
    csr_zero<<<ZGRID, EB>>>();
    csr_hist<<<E4GRID, EB>>>(ei);
    csr_scan<<<1, 1024>>>();
    csr_scatter<<<E4GRID, EB>>>(ei);

    // ---- layer 0 (in=32, no residual) ----
    gemm_fused<32, false><<<GGRID, 256>>>(x, W0, as0, ad0);
    gat_fused96<false><<<WGRID, EB>>>(b0);

    // ---- layer 1 (in=96, residual) ----
    gemm_fused<96, true><<<GGRID, 256>>>(nullptr, W1, as1, ad1);
    gat_fused96<true><<<WGRID, EB>>>(b1);

    // ---- layer 2 (in=96, residual) ----
    gemm_fused<96, true><<<GGRID, 256>>>(nullptr, W2, as2, ad2);
    gat_fused96<true><<<WGRID, EB>>>(b2);

    // ---- final layer (out=1) ----
    gemm_logits_f<<<WGRID, EB>>>(Wf, asf, adf);
    gat_fused1<<<WGRID, EB>>>(bf, dout);
}

// round 10
// speedup vs baseline: 2.7073x; 1.1985x over previous
#include <cuda_runtime.h>
#include <cstdint>

#define N_NODES 50000
#define N_EDGES 800000
#define E_TOT   (N_EDGES + N_NODES)   // self loops appended
#define HID     96
#define HROW    128                   // padded h row (512B) for float4 gathers
#define NEG_SLOPE 0.2f

// ---------------- scratch (allocation-free: device globals) ----------------
__device__ float g_x[N_NODES * HID];    // current layer input features
__device__ float g_h[N_NODES * HROW];   // h = x @ W, padded rows (zero pad)
__device__ float g_es[N_NODES];
__device__ float g_ed[N_NODES];
// CSR (rebuilt every launch; edges are launch-invariant inputs)
__device__ int g_cnt[N_NODES];
__device__ int g_rp [N_NODES + 1];
__device__ int g_cur[N_NODES];
__device__ int g_csrc[E_TOT];

#define SCAN_B  256
#define SCAN_NB ((N_NODES + SCAN_B - 1) / SCAN_B)   // 196
__device__ int g_blk[SCAN_NB];
__device__ int g_blkoff[SCAN_NB];

__device__ __forceinline__ float lrelu(float e) {
    return (e > 0.f) ? e : NEG_SLOPE * e;
}

// packed f32x2 helpers (FFMA2 is PTX-only on sm_103a)
__device__ __forceinline__ unsigned long long pack2(float lo, float hi) {
    unsigned long long r;
    asm("mov.b64 %0, {%1, %2};" : "=l"(r) : "f"(lo), "f"(hi));
    return r;
}
__device__ __forceinline__ void unpack2(unsigned long long v, float& lo, float& hi) {
    asm("mov.b64 {%0, %1}, %2;" : "=f"(lo), "=f"(hi) : "l"(v));
}
__device__ __forceinline__ unsigned long long fma2(unsigned long long a,
                                                   unsigned long long b,
                                                   unsigned long long c) {
    unsigned long long d;
    asm("fma.rn.f32x2 %0, %1, %2, %3;" : "=l"(d) : "l"(a), "l"(b), "l"(c));
    return d;
}
__device__ __forceinline__ unsigned long long mul2(unsigned long long a,
                                                   unsigned long long b) {
    unsigned long long d;
    asm("mul.rn.f32x2 %0, %1, %2;" : "=l"(d) : "l"(a), "l"(b));
    return d;
}

// ---------------- CSR build ----------------
__global__ void csr_zero() {
    int i = blockIdx.x * blockDim.x + threadIdx.x;
    if (i < N_NODES) g_cnt[i] = 0;
}

// 4 edges per thread for MLP
__global__ void csr_hist(const int* __restrict__ ei) {
    int base = (blockIdx.x * blockDim.x + threadIdx.x) * 4;
    int d[4];
#pragma unroll
    for (int u = 0; u < 4; u++) {
        int i = base + u;
        d[u] = (i < E_TOT) ? ((i < N_EDGES) ? __ldg(ei + N_EDGES + i) : (i - N_EDGES)) : -1;
    }
#pragma unroll
    for (int u = 0; u < 4; u++)
        if (d[u] >= 0) atomicAdd(&g_cnt[d[u]], 1);
}

// -------- multi-block exclusive scan: part -> tops -> apply --------
__global__ void scan_part() {
    __shared__ int sh[SCAN_B];
    int t = threadIdx.x;
    int i = blockIdx.x * SCAN_B + t;
    sh[t] = (i < N_NODES) ? g_cnt[i] : 0;
    __syncthreads();
    for (int off = SCAN_B / 2; off; off >>= 1) {
        if (t < off) sh[t] += sh[t + off];
        __syncthreads();
    }
    if (t == 0) g_blk[blockIdx.x] = sh[0];
}

__global__ void scan_tops() {     // 1 block scans SCAN_NB partials
    __shared__ int sh[SCAN_B];
    int t = threadIdx.x;
    sh[t] = (t < SCAN_NB) ? g_blk[t] : 0;
    __syncthreads();
    for (int off = 1; off < SCAN_B; off <<= 1) {
        int v = (t >= off) ? sh[t - off] : 0;
        __syncthreads();
        sh[t] += v;
        __syncthreads();
    }
    if (t < SCAN_NB) g_blkoff[t] = (t > 0) ? sh[t - 1] : 0;
}

__global__ void scan_apply() {
    __shared__ int sh[SCAN_B];
    int t = threadIdx.x;
    int i = blockIdx.x * SCAN_B + t;
    int v = (i < N_NODES) ? g_cnt[i] : 0;
    sh[t] = v;
    __syncthreads();
    for (int off = 1; off < SCAN_B; off <<= 1) {
        int u = (t >= off) ? sh[t - off] : 0;
        __syncthreads();
        sh[t] += u;
        __syncthreads();
    }
    int excl = sh[t] - v + g_blkoff[blockIdx.x];
    if (i < N_NODES) { g_rp[i] = excl; g_cur[i] = excl; }
    if (blockIdx.x == gridDim.x - 1 && t == SCAN_B - 1) g_rp[N_NODES] = E_TOT;
}

// 4 edges per thread for MLP
__global__ void csr_scatter(const int* __restrict__ ei) {
    int base = (blockIdx.x * blockDim.x + threadIdx.x) * 4;
    int s[4], d[4];
#pragma unroll
    for (int u = 0; u < 4; u++) {
        int i = base + u;
        if (i < N_EDGES)     { s[u] = __ldg(ei + i); d[u] = __ldg(ei + N_EDGES + i); }
        else if (i < E_TOT)  { s[u] = d[u] = i - N_EDGES; }
        else                 { d[u] = -1; }
    }
#pragma unroll
    for (int u = 0; u < 4; u++) {
        if (d[u] >= 0) {
            int pos = atomicAdd(&g_cur[d[u]], 1);
            g_csrc[pos] = s[u];
        }
    }
}

// ---------------- GEMM + fused logits: h = x@W, es = h.as, ed = h.ad --------
// 256 threads, 64 nodes/block. Thread t: c = t&15 -> col pairs {2c,2c+1}+32u
// (u=0..2), r = t>>4 -> nodes r*4+v (v=0..3). 12 FFMA2 per k-step.
template<int K, bool FROM_GX>
__global__ __launch_bounds__(256) void gemm_fused(const float* __restrict__ xin,
                                                  const float* __restrict__ W,
                                                  const float* __restrict__ as_,
                                                  const float* __restrict__ ad_) {
    __shared__ float xs[K][68];
    int t  = threadIdx.x;
    int nb = blockIdx.x * 64;

    const float* xsrc = FROM_GX ? g_x : xin;
    for (int idx = t; idx < 64 * K; idx += 256) {
        int n = idx / K, k = idx - n * K;
        int gn = nb + n;
        xs[k][n] = (gn < N_NODES) ? xsrc[(size_t)gn * K + k] : 0.f;
    }
    __syncthreads();

    int c = t & 15;
    int r = t >> 4;

    unsigned long long acc[4][3];
#pragma unroll
    for (int v = 0; v < 4; v++)
#pragma unroll
        for (int u = 0; u < 3; u++) acc[v][u] = 0ull;

#pragma unroll 4
    for (int k = 0; k < K; k++) {
        float4 xv = *reinterpret_cast<const float4*>(&xs[k][r * 4]);
        const float* wr = W + (size_t)k * HID + 2 * c;
        unsigned long long w0 = __ldg((const unsigned long long*)(wr));
        unsigned long long w1 = __ldg((const unsigned long long*)(wr + 32));
        unsigned long long w2 = __ldg((const unsigned long long*)(wr + 64));
        unsigned long long x0 = pack2(xv.x, xv.x);
        unsigned long long x1 = pack2(xv.y, xv.y);
        unsigned long long x2 = pack2(xv.z, xv.z);
        unsigned long long x3 = pack2(xv.w, xv.w);
        acc[0][0] = fma2(x0, w0, acc[0][0]);
        acc[0][1] = fma2(x0, w1, acc[0][1]);
        acc[0][2] = fma2(x0, w2, acc[0][2]);
        acc[1][0] = fma2(x1, w0, acc[1][0]);
        acc[1][1] = fma2(x1, w1, acc[1][1]);
        acc[1][2] = fma2(x1, w2, acc[1][2]);
        acc[2][0] = fma2(x2, w0, acc[2][0]);
        acc[2][1] = fma2(x2, w1, acc[2][1]);
        acc[2][2] = fma2(x2, w2, acc[2][2]);
        acc[3][0] = fma2(x3, w0, acc[3][0]);
        acc[3][1] = fma2(x3, w1, acc[3][1]);
        acc[3][2] = fma2(x3, w2, acc[3][2]);
    }

    float as0, as1, as2, as3, as4, as5, ad0, ad1, ad2, ad3, ad4, ad5;
    {
        float2 a = __ldg((const float2*)(as_ + 2 * c));
        float2 b = __ldg((const float2*)(as_ + 2 * c + 32));
        float2 d = __ldg((const float2*)(as_ + 2 * c + 64));
        as0 = a.x; as1 = a.y; as2 = b.x; as3 = b.y; as4 = d.x; as5 = d.y;
        a = __ldg((const float2*)(ad_ + 2 * c));
        b = __ldg((const float2*)(ad_ + 2 * c + 32));
        d = __ldg((const float2*)(ad_ + 2 * c + 64));
        ad0 = a.x; ad1 = a.y; ad2 = b.x; ad3 = b.y; ad4 = d.x; ad5 = d.y;
    }

#pragma unroll
    for (int v = 0; v < 4; v++) {
        float h0, h1, h2, h3, h4, h5;
        unpack2(acc[v][0], h0, h1);
        unpack2(acc[v][1], h2, h3);
        unpack2(acc[v][2], h4, h5);
        int n = nb + r * 4 + v;
        if (n < N_NODES) {
            float* hr = g_h + (size_t)n * HROW + 2 * c;
            *(float2*)(hr)      = make_float2(h0, h1);
            *(float2*)(hr + 32) = make_float2(h2, h3);
            *(float2*)(hr + 64) = make_float2(h4, h5);
        }
        float ps = h0 * as0 + h1 * as1 + h2 * as2 + h3 * as3 + h4 * as4 + h5 * as5;
        float pd = h0 * ad0 + h1 * ad1 + h2 * ad2 + h3 * ad3 + h4 * ad4 + h5 * ad5;
#pragma unroll
        for (int o = 8; o; o >>= 1) {
            ps += __shfl_down_sync(0xffffffffu, ps, o, 16);
            pd += __shfl_down_sync(0xffffffffu, pd, o, 16);
        }
        if (c == 0 && n < N_NODES) { g_es[n] = ps; g_ed[n] = pd; }
    }
}

// final layer gemm: out_dim = 1, warp per node (g_h used as [N] scalar array)
__global__ void gemm_logits_f(const float* __restrict__ W,
                              const float* __restrict__ as_,
                              const float* __restrict__ ad_) {
    int n = blockIdx.x * (blockDim.x >> 5) + (threadIdx.x >> 5);
    if (n >= N_NODES) return;
    int lane = threadIdx.x & 31;
    float acc = 0.f;
#pragma unroll
    for (int k = lane; k < HID; k += 32) acc += g_x[(size_t)n * HID + k] * __ldg(W + k);
#pragma unroll
    for (int o = 16; o; o >>= 1) acc += __shfl_down_sync(0xffffffffu, acc, o);
    if (lane == 0) {
        g_h[n]  = acc;
        g_es[n] = acc * __ldg(as_);
        g_ed[n] = acc * __ldg(ad_);
    }
}

// ---------------- fused attention + aggregation (wide layers) ----------------
// Warp per dst node, online softmax at chunk-of-32 granularity.
// Lane l accumulates features [4l, 4l+4) via one LDG.128 + 2 FFMA2 per edge.
// exp() hoisted out of the inner loop (once per lane per chunk).
template<bool RESIDUAL>
__global__ void gat_fused96(const float* __restrict__ b) {
    int n = blockIdx.x * (blockDim.x >> 5) + (threadIdx.x >> 5);
    if (n >= N_NODES) return;
    int lane = threadIdx.x & 31;
    int beg = g_rp[n], end = g_rp[n + 1];
    float edv = g_ed[n];

    float m = -1e30f, s = 0.f;
    unsigned long long acc01 = 0ull, acc23 = 0ull;

    for (int cb = beg; cb < end; cb += 32) {
        int nedge = min(32, end - cb);
        int ii = cb + lane;
        int srcl = (ii < end) ? g_csrc[ii] : 0;
        float el = (ii < end) ? lrelu(g_es[srcl] + edv) : -1e30f;

        float mc = el;
#pragma unroll
        for (int o = 16; o; o >>= 1)
            mc = fmaxf(mc, __shfl_xor_sync(0xffffffffu, mc, o));
        float mn = fmaxf(m, mc);
        float scale = __expf(m - mn);   // first chunk: 0
        m = mn;

        float exl = __expf(el - m);     // inactive lanes: exp(-huge) = 0
        float sc = exl;
#pragma unroll
        for (int o = 16; o; o >>= 1)
            sc += __shfl_xor_sync(0xffffffffu, sc, o);
        s = s * scale + sc;

        unsigned long long sc2 = pack2(scale, scale);
        acc01 = mul2(acc01, sc2);
        acc23 = mul2(acc23, sc2);

#pragma unroll 4
        for (int j = 0; j < nedge; j++) {
            float ex = __shfl_sync(0xffffffffu, exl,  j);
            int   sj = __shfl_sync(0xffffffffu, srcl, j);
            float4 hv = *(const float4*)(g_h + (size_t)sj * HROW + 4 * lane);
            unsigned long long ex2 = pack2(ex, ex);
            acc01 = fma2(pack2(hv.x, hv.y), ex2, acc01);
            acc23 = fma2(pack2(hv.z, hv.w), ex2, acc23);
        }
    }

    if (lane < 24) {   // lanes 0..23 hold the 96 real features
        float a0, a1, a2, a3;
        unpack2(acc01, a0, a1);
        unpack2(acc23, a2, a3);
        float inv = 1.f / s;
        float4 bb = __ldg((const float4*)(b + 4 * lane));
        float* xr = g_x + (size_t)n * HID + 4 * lane;
        float v0 = a0 * inv + bb.x;
        float v1 = a1 * inv + bb.y;
        float v2 = a2 * inv + bb.z;
        float v3 = a3 * inv + bb.w;
        if (RESIDUAL) {
            float4 xv = *(const float4*)xr;
            v0 += xv.x; v1 += xv.y; v2 += xv.z; v3 += xv.w;
        }
        *(float4*)xr = make_float4(fmaxf(v0, 0.f), fmaxf(v1, 0.f),
                                   fmaxf(v2, 0.f), fmaxf(v3, 0.f));
    }
}

// final layer: out_dim = 1, lanes parallel over edges
__global__ void gat_fused1(const float* __restrict__ b, float* __restrict__ dout) {
    int n = blockIdx.x * (blockDim.x >> 5) + (threadIdx.x >> 5);
    if (n >= N_NODES) return;
    int lane = threadIdx.x & 31;
    int beg = g_rp[n], end = g_rp[n + 1];
    float edv = g_ed[n];

    float m = -1e30f;
    for (int i = beg + lane; i < end; i += 32)
        m = fmaxf(m, lrelu(g_es[g_csrc[i]] + edv));
#pragma unroll
    for (int o = 16; o; o >>= 1)
        m = fmaxf(m, __shfl_xor_sync(0xffffffffu, m, o));

    float s = 0.f, num = 0.f;
    for (int i = beg + lane; i < end; i += 32) {
        int src = g_csrc[i];
        float ex = __expf(lrelu(g_es[src] + edv) - m);
        s += ex;
        num = fmaf(ex, g_h[src], num);
    }
#pragma unroll
    for (int o = 16; o; o >>= 1) {
        s   += __shfl_xor_sync(0xffffffffu, s, o);
        num += __shfl_xor_sync(0xffffffffu, num, o);
    }
    if (lane == 0) dout[n] = num / s + __ldg(b);
}

// ---------------- launch ----------------
extern "C" void kernel_launch(void* const* d_in, const int* in_sizes, int n_in,
                              void* d_out, int out_size) {
    const float* x  = (const float*)d_in[0];
    const int*   ei = (const int*)d_in[1];   // int32 [2, E]
    // d_in[2] = edge_weight (ignored, matches reference)
    const float* W0 = (const float*)d_in[3];
    const float* as0 = (const float*)d_in[4];
    const float* ad0 = (const float*)d_in[5];
    const float* b0 = (const float*)d_in[6];
    const float* W1 = (const float*)d_in[7];
    const float* as1 = (const float*)d_in[8];
    const float* ad1 = (const float*)d_in[9];
    const float* b1 = (const float*)d_in[10];
    const float* W2 = (const float*)d_in[11];
    const float* as2 = (const float*)d_in[12];
    const float* ad2 = (const float*)d_in[13];
    const float* b2 = (const float*)d_in[14];
    const float* Wf = (const float*)d_in[15];
    const float* asf = (const float*)d_in[16];
    const float* adf = (const float*)d_in[17];
    const float* bf = (const float*)d_in[18];
    float* dout = (float*)d_out;

    const int EB = 256;
    const int E4GRID = (E_TOT + EB * 4 - 1) / (EB * 4);       // 4 edges/thread
    const int WGRID  = (N_NODES + (EB / 32) - 1) / (EB / 32); // warp-per-node
    const int ZGRID  = (N_NODES + EB - 1) / EB;
    const int GGRID  = (N_NODES + 63) / 64;                   // 64 nodes per gemm block

    // ---- CSR build (once; edges identical for all layers) ----
    csr_zero<<<ZGRID, EB>>>();
    csr_hist<<<E4GRID, EB>>>(ei);
    scan_part<<<SCAN_NB, SCAN_B>>>();
    scan_tops<<<1, SCAN_B>>>();
    scan_apply<<<SCAN_NB, SCAN_B>>>();
    csr_scatter<<<E4GRID, EB>>>(ei);

    // ---- layer 0 (in=32, no residual) ----
    gemm_fused<32, false><<<GGRID, 256>>>(x, W0, as0, ad0);
    gat_fused96<false><<<WGRID, EB>>>(b0);

    // ---- layer 1 (in=96, residual) ----
    gemm_fused<96, true><<<GGRID, 256>>>(nullptr, W1, as1, ad1);
    gat_fused96<true><<<WGRID, EB>>>(b1);

    // ---- layer 2 (in=96, residual) ----
    gemm_fused<96, true><<<GGRID, 256>>>(nullptr, W2, as2, ad2);
    gat_fused96<true><<<WGRID, EB>>>(b2);

    // ---- final layer (out=1) ----
    gemm_logits_f<<<WGRID, EB>>>(Wf, asf, adf);
    gat_fused1<<<WGRID, EB>>>(bf, dout);
}

// round 14
// speedup vs baseline: 2.9140x; 1.0764x over previous
#include <cuda_runtime.h>
#include <cstdint>

#define N_NODES 50000
#define N_EDGES 800000
#define E_TOT   (N_EDGES + N_NODES)   // self loops appended
#define HID     96
#define NEG_SLOPE 0.2f

// ---------------- scratch (allocation-free: device globals) ----------------
__device__ float g_x[N_NODES * HID];    // current layer input features
__device__ float g_h[N_NODES * HID];    // h = x @ W
__device__ float g_es[N_NODES];
__device__ float g_ed[N_NODES];
// final-layer scalar buffers (separate to avoid RAW race in fused epilogue)
__device__ float g_hf[N_NODES];
__device__ float g_esf[N_NODES];
__device__ float g_edf[N_NODES];
// CSR (rebuilt every launch; edges are launch-invariant inputs)
__device__ int g_cnt[N_NODES];
__device__ int g_rp [N_NODES + 1];
__device__ int g_cur[N_NODES];
__device__ int g_csrc[E_TOT];

#define SCAN_B  256
#define SCAN_NB ((N_NODES + SCAN_B - 1) / SCAN_B)   // 196
__device__ int g_blk[SCAN_NB];
__device__ int g_blkoff[SCAN_NB];

__device__ __forceinline__ float lrelu(float e) {
    return (e > 0.f) ? e : NEG_SLOPE * e;
}

// packed f32x2 helpers (FFMA2 is PTX-only on sm_103a)
__device__ __forceinline__ unsigned long long pack2(float lo, float hi) {
    unsigned long long r;
    asm("mov.b64 %0, {%1, %2};" : "=l"(r) : "f"(lo), "f"(hi));
    return r;
}
__device__ __forceinline__ void unpack2(unsigned long long v, float& lo, float& hi) {
    asm("mov.b64 {%0, %1}, %2;" : "=f"(lo), "=f"(hi) : "l"(v));
}
__device__ __forceinline__ unsigned long long fma2(unsigned long long a,
                                                   unsigned long long b,
                                                   unsigned long long c) {
    unsigned long long d;
    asm("fma.rn.f32x2 %0, %1, %2, %3;" : "=l"(d) : "l"(a), "l"(b), "l"(c));
    return d;
}
__device__ __forceinline__ unsigned long long mul2(unsigned long long a,
                                                   unsigned long long b) {
    unsigned long long d;
    asm("mul.rn.f32x2 %0, %1, %2;" : "=l"(d) : "l"(a), "l"(b));
    return d;
}

// ---------------- CSR build ----------------
__global__ void csr_zero() {
    int i = blockIdx.x * blockDim.x + threadIdx.x;
    if (i < N_NODES) g_cnt[i] = 0;
}

// 4 edges per thread for MLP
__global__ void csr_hist(const int* __restrict__ ei) {
    int base = (blockIdx.x * blockDim.x + threadIdx.x) * 4;
    int d[4];
#pragma unroll
    for (int u = 0; u < 4; u++) {
        int i = base + u;
        d[u] = (i < E_TOT) ? ((i < N_EDGES) ? __ldg(ei + N_EDGES + i) : (i - N_EDGES)) : -1;
    }
#pragma unroll
    for (int u = 0; u < 4; u++)
        if (d[u] >= 0) atomicAdd(&g_cnt[d[u]], 1);
}

// -------- multi-block exclusive scan: part -> tops -> apply --------
__global__ void scan_part() {
    __shared__ int sh[SCAN_B];
    int t = threadIdx.x;
    int i = blockIdx.x * SCAN_B + t;
    sh[t] = (i < N_NODES) ? g_cnt[i] : 0;
    __syncthreads();
    for (int off = SCAN_B / 2; off; off >>= 1) {
        if (t < off) sh[t] += sh[t + off];
        __syncthreads();
    }
    if (t == 0) g_blk[blockIdx.x] = sh[0];
}

__global__ void scan_tops() {     // 1 block scans SCAN_NB partials
    __shared__ int sh[SCAN_B];
    int t = threadIdx.x;
    sh[t] = (t < SCAN_NB) ? g_blk[t] : 0;
    __syncthreads();
    for (int off = 1; off < SCAN_B; off <<= 1) {
        int v = (t >= off) ? sh[t - off] : 0;
        __syncthreads();
        sh[t] += v;
        __syncthreads();
    }
    if (t < SCAN_NB) g_blkoff[t] = (t > 0) ? sh[t - 1] : 0;
}

__global__ void scan_apply() {
    __shared__ int sh[SCAN_B];
    int t = threadIdx.x;
    int i = blockIdx.x * SCAN_B + t;
    int v = (i < N_NODES) ? g_cnt[i] : 0;
    sh[t] = v;
    __syncthreads();
    for (int off = 1; off < SCAN_B; off <<= 1) {
        int u = (t >= off) ? sh[t - off] : 0;
        __syncthreads();
        sh[t] += u;
        __syncthreads();
    }
    int excl = sh[t] - v + g_blkoff[blockIdx.x];
    if (i < N_NODES) { g_rp[i] = excl; g_cur[i] = excl; }
    if (blockIdx.x == gridDim.x - 1 && t == SCAN_B - 1) g_rp[N_NODES] = E_TOT;
}

// 4 edges per thread for MLP
__global__ void csr_scatter(const int* __restrict__ ei) {
    int base = (blockIdx.x * blockDim.x + threadIdx.x) * 4;
    int s[4], d[4];
#pragma unroll
    for (int u = 0; u < 4; u++) {
        int i = base + u;
        if (i < N_EDGES)     { s[u] = __ldg(ei + i); d[u] = __ldg(ei + N_EDGES + i); }
        else if (i < E_TOT)  { s[u] = d[u] = i - N_EDGES; }
        else                 { d[u] = -1; }
    }
#pragma unroll
    for (int u = 0; u < 4; u++) {
        if (d[u] >= 0) {
            int pos = atomicAdd(&g_cur[d[u]], 1);
            g_csrc[pos] = s[u];
        }
    }
}

// ---------------- GEMM + fused logits: h = x@W, es = h.as, ed = h.ad --------
// 256 threads, 64 nodes/block. Thread t: c = t&15 -> col pairs {2c,2c+1}+32u
// (u=0..2), r = t>>4 -> nodes r*4+v (v=0..3). 12 FFMA2 per k-step.
template<int K, bool FROM_GX>
__global__ __launch_bounds__(256) void gemm_fused(const float* __restrict__ xin,
                                                  const float* __restrict__ W,
                                                  const float* __restrict__ as_,
                                                  const float* __restrict__ ad_) {
    __shared__ float xs[K][68];
    int t  = threadIdx.x;
    int nb = blockIdx.x * 64;

    const float* xsrc = FROM_GX ? g_x : xin;
    for (int idx = t; idx < 64 * K; idx += 256) {
        int n = idx / K, k = idx - n * K;
        int gn = nb + n;
        xs[k][n] = (gn < N_NODES) ? xsrc[(size_t)gn * K + k] : 0.f;
    }
    __syncthreads();

    int c = t & 15;
    int r = t >> 4;

    unsigned long long acc[4][3];
#pragma unroll
    for (int v = 0; v < 4; v++)
#pragma unroll
        for (int u = 0; u < 3; u++) acc[v][u] = 0ull;

#pragma unroll 4
    for (int k = 0; k < K; k++) {
        float4 xv = *reinterpret_cast<const float4*>(&xs[k][r * 4]);
        const float* wr = W + (size_t)k * HID + 2 * c;
        unsigned long long w0 = __ldg((const unsigned long long*)(wr));
        unsigned long long w1 = __ldg((const unsigned long long*)(wr + 32));
        unsigned long long w2 = __ldg((const unsigned long long*)(wr + 64));
        unsigned long long x0 = pack2(xv.x, xv.x);
        unsigned long long x1 = pack2(xv.y, xv.y);
        unsigned long long x2 = pack2(xv.z, xv.z);
        unsigned long long x3 = pack2(xv.w, xv.w);
        acc[0][0] = fma2(x0, w0, acc[0][0]);
        acc[0][1] = fma2(x0, w1, acc[0][1]);
        acc[0][2] = fma2(x0, w2, acc[0][2]);
        acc[1][0] = fma2(x1, w0, acc[1][0]);
        acc[1][1] = fma2(x1, w1, acc[1][1]);
        acc[1][2] = fma2(x1, w2, acc[1][2]);
        acc[2][0] = fma2(x2, w0, acc[2][0]);
        acc[2][1] = fma2(x2, w1, acc[2][1]);
        acc[2][2] = fma2(x2, w2, acc[2][2]);
        acc[3][0] = fma2(x3, w0, acc[3][0]);
        acc[3][1] = fma2(x3, w1, acc[3][1]);
        acc[3][2] = fma2(x3, w2, acc[3][2]);
    }

    float as0, as1, as2, as3, as4, as5, ad0, ad1, ad2, ad3, ad4, ad5;
    {
        float2 a = __ldg((const float2*)(as_ + 2 * c));
        float2 b = __ldg((const float2*)(as_ + 2 * c + 32));
        float2 d = __ldg((const float2*)(as_ + 2 * c + 64));
        as0 = a.x; as1 = a.y; as2 = b.x; as3 = b.y; as4 = d.x; as5 = d.y;
        a = __ldg((const float2*)(ad_ + 2 * c));
        b = __ldg((const float2*)(ad_ + 2 * c + 32));
        d = __ldg((const float2*)(ad_ + 2 * c + 64));
        ad0 = a.x; ad1 = a.y; ad2 = b.x; ad3 = b.y; ad4 = d.x; ad5 = d.y;
    }

#pragma unroll
    for (int v = 0; v < 4; v++) {
        float h0, h1, h2, h3, h4, h5;
        unpack2(acc[v][0], h0, h1);
        unpack2(acc[v][1], h2, h3);
        unpack2(acc[v][2], h4, h5);
        int n = nb + r * 4 + v;
        if (n < N_NODES) {
            float* hr = g_h + (size_t)n * HID + 2 * c;
            *(float2*)(hr)      = make_float2(h0, h1);
            *(float2*)(hr + 32) = make_float2(h2, h3);
            *(float2*)(hr + 64) = make_float2(h4, h5);
        }
        float ps = h0 * as0 + h1 * as1 + h2 * as2 + h3 * as3 + h4 * as4 + h5 * as5;
        float pd = h0 * ad0 + h1 * ad1 + h2 * ad2 + h3 * ad3 + h4 * ad4 + h5 * ad5;
#pragma unroll
        for (int o = 8; o; o >>= 1) {
            ps += __shfl_down_sync(0xffffffffu, ps, o, 16);
            pd += __shfl_down_sync(0xffffffffu, pd, o, 16);
        }
        if (c == 0 && n < N_NODES) { g_es[n] = ps; g_ed[n] = pd; }
    }
}

// ---------------- fused attention + aggregation (wide layers) ----------------
// Warp per dst node, online softmax at chunk-of-32 granularity.
// Lanes 0..23 each gather features [4l,4l+4) via one LDG.128 + 2 FFMA2 per edge.
// FINAL: also compute hf = relu_out . Wf + its logits, into SEPARATE buffers
// (g_hf/g_esf/g_edf) so the layer-2 inputs g_h/g_es/g_ed are never overwritten
// while other blocks still read them.
template<bool RESIDUAL, bool FINAL>
__global__ void gat_fused96(const float* __restrict__ b,
                            const float* __restrict__ Wf,
                            const float* __restrict__ asf,
                            const float* __restrict__ adf) {
    int n = blockIdx.x * (blockDim.x >> 5) + (threadIdx.x >> 5);
    if (n >= N_NODES) return;
    int lane = threadIdx.x & 31;
    int beg = g_rp[n], end = g_rp[n + 1];
    float edv = g_ed[n];

    float m = -1e30f, s = 0.f;
    unsigned long long acc01 = 0ull, acc23 = 0ull;

    for (int cb = beg; cb < end; cb += 32) {
        int nedge = min(32, end - cb);
        int ii = cb + lane;
        int srcl = (ii < end) ? g_csrc[ii] : 0;
        float el = (ii < end) ? lrelu(g_es[srcl] + edv) : -1e30f;

        float mc = el;
#pragma unroll
        for (int o = 16; o; o >>= 1)
            mc = fmaxf(mc, __shfl_xor_sync(0xffffffffu, mc, o));
        float mn = fmaxf(m, mc);
        float scale = __expf(m - mn);   // first chunk: 0
        m = mn;

        float exl = __expf(el - m);     // inactive lanes: exp(-huge) = 0
        float sc = exl;
#pragma unroll
        for (int o = 16; o; o >>= 1)
            sc += __shfl_xor_sync(0xffffffffu, sc, o);
        s = s * scale + sc;

        unsigned long long sc2 = pack2(scale, scale);
        acc01 = mul2(acc01, sc2);
        acc23 = mul2(acc23, sc2);

#pragma unroll 4
        for (int j = 0; j < nedge; j++) {
            float ex = __shfl_sync(0xffffffffu, exl,  j);
            int   sj = __shfl_sync(0xffffffffu, srcl, j);
            float4 hv = make_float4(0.f, 0.f, 0.f, 0.f);
            if (lane < 24)
                hv = *(const float4*)(g_h + (size_t)sj * HID + 4 * lane);
            unsigned long long ex2 = pack2(ex, ex);
            acc01 = fma2(pack2(hv.x, hv.y), ex2, acc01);
            acc23 = fma2(pack2(hv.z, hv.w), ex2, acc23);
        }
    }

    float part = 0.f;
    if (lane < 24) {   // lanes 0..23 hold the 96 real features
        float a0, a1, a2, a3;
        unpack2(acc01, a0, a1);
        unpack2(acc23, a2, a3);
        float inv = 1.f / s;
        float4 bb = __ldg((const float4*)(b + 4 * lane));
        float* xr = g_x + (size_t)n * HID + 4 * lane;
        float v0 = a0 * inv + bb.x;
        float v1 = a1 * inv + bb.y;
        float v2 = a2 * inv + bb.z;
        float v3 = a3 * inv + bb.w;
        if (RESIDUAL) {
            float4 xv = *(const float4*)xr;
            v0 += xv.x; v1 += xv.y; v2 += xv.z; v3 += xv.w;
        }
        v0 = fmaxf(v0, 0.f); v1 = fmaxf(v1, 0.f);
        v2 = fmaxf(v2, 0.f); v3 = fmaxf(v3, 0.f);
        if (!FINAL) {
            *(float4*)xr = make_float4(v0, v1, v2, v3);
        } else {
            float4 wv = __ldg((const float4*)(Wf + 4 * lane));
            part = v0 * wv.x + v1 * wv.y + v2 * wv.z + v3 * wv.w;
        }
    }
    if (FINAL) {
#pragma unroll
        for (int o = 16; o; o >>= 1)
            part += __shfl_xor_sync(0xffffffffu, part, o);
        if (lane == 0) {
            g_hf[n]  = part;
            g_esf[n] = part * __ldg(asf);
            g_edf[n] = part * __ldg(adf);
        }
    }
}

// final layer: out_dim = 1, lanes parallel over edges (reads g_hf/g_esf/g_edf)
__global__ void gat_fused1(const float* __restrict__ b, float* __restrict__ dout) {
    int n = blockIdx.x * (blockDim.x >> 5) + (threadIdx.x >> 5);
    if (n >= N_NODES) return;
    int lane = threadIdx.x & 31;
    int beg = g_rp[n], end = g_rp[n + 1];
    float edv = g_edf[n];

    float m = -1e30f;
    for (int i = beg + lane; i < end; i += 32)
        m = fmaxf(m, lrelu(g_esf[g_csrc[i]] + edv));
#pragma unroll
    for (int o = 16; o; o >>= 1)
        m = fmaxf(m, __shfl_xor_sync(0xffffffffu, m, o));

    float s = 0.f, num = 0.f;
    for (int i = beg + lane; i < end; i += 32) {
        int src = g_csrc[i];
        float ex = __expf(lrelu(g_esf[src] + edv) - m);
        s += ex;
        num = fmaf(ex, g_hf[src], num);
    }
#pragma unroll
    for (int o = 16; o; o >>= 1) {
        s   += __shfl_xor_sync(0xffffffffu, s, o);
        num += __shfl_xor_sync(0xffffffffu, num, o);
    }
    if (lane == 0) dout[n] = num / s + __ldg(b);
}

// ---------------- launch ----------------
extern "C" void kernel_launch(void* const* d_in, const int* in_sizes, int n_in,
                              void* d_out, int out_size) {
    const float* x  = (const float*)d_in[0];
    const int*   ei = (const int*)d_in[1];   // int32 [2, E]
    // d_in[2] = edge_weight (ignored, matches reference)
    const float* W0 = (const float*)d_in[3];
    const float* as0 = (const float*)d_in[4];
    const float* ad0 = (const float*)d_in[5];
    const float* b0 = (const float*)d_in[6];
    const float* W1 = (const float*)d_in[7];
    const float* as1 = (const float*)d_in[8];
    const float* ad1 = (const float*)d_in[9];
    const float* b1 = (const float*)d_in[10];
    const float* W2 = (const float*)d_in[11];
    const float* as2 = (const float*)d_in[12];
    const float* ad2 = (const float*)d_in[13];
    const float* b2 = (const float*)d_in[14];
    const float* Wf = (const float*)d_in[15];
    const float* asf = (const float*)d_in[16];
    const float* adf = (const float*)d_in[17];
    const float* bf = (const float*)d_in[18];
    float* dout = (float*)d_out;

    const int EB = 256;
    const int E4GRID = (E_TOT + EB * 4 - 1) / (EB * 4);       // 4 edges/thread
    const int WGRID  = (N_NODES + (EB / 32) - 1) / (EB / 32); // warp-per-node
    const int ZGRID  = (N_NODES + EB - 1) / EB;
    const int GGRID  = (N_NODES + 63) / 64;                   // 64 nodes per gemm block

    // ---- CSR build (once; edges identical for all layers) ----
    csr_zero<<<ZGRID, EB>>>();
    csr_hist<<<E4GRID, EB>>>(ei);
    scan_part<<<SCAN_NB, SCAN_B>>>();
    scan_tops<<<1, SCAN_B>>>();
    scan_apply<<<SCAN_NB, SCAN_B>>>();
    csr_scatter<<<E4GRID, EB>>>(ei);

    // ---- layer 0 (in=32, no residual) ----
    gemm_fused<32, false><<<GGRID, 256>>>(x, W0, as0, ad0);
    gat_fused96<false, false><<<WGRID, EB>>>(b0, nullptr, nullptr, nullptr);

    // ---- layer 1 (in=96, residual) ----
    gemm_fused<96, true><<<GGRID, 256>>>(nullptr, W1, as1, ad1);
    gat_fused96<true, false><<<WGRID, EB>>>(b1, nullptr, nullptr, nullptr);

    // ---- layer 2 (in=96, residual) + fused final scalar gemm/logits ----
    gemm_fused<96, true><<<GGRID, 256>>>(nullptr, W2, as2, ad2);
    gat_fused96<true, true><<<WGRID, EB>>>(b2, Wf, asf, adf);

    // ---- final layer aggregation (out=1) ----
    gat_fused1<<<WGRID, EB>>>(bf, dout);
}